// round 10
// baseline (speedup 1.0000x reference)
#include <cuda_runtime.h>

#define BB 2
#define DM 192
#define DI 384
#define DS 16
#define DR 12
#define HH 64
#define WW 64
#define LL 4096
#define NROWS (BB*LL)   // 8192

#define TSTEP 32
#define CH 32
#define CL (LL/CH)          // 128 steps per chunk
#define PTILES (CL/TSTEP)   // 4 tiles per chunk

// ---------------- scratch ----------------
__device__ float  g_xa_pre[BB*DI*LL];
__device__ float  g_c_pre [BB*DI*LL];
__device__ float  g_xa_conv[BB*DI*LL];
__device__ float  g_s     [BB*DI*LL];
__device__ float  g_z     [NROWS*DI];
__device__ float2 g_du    [BB*LL*DI];
__device__ float2 g_bc    [BB*LL*DS];
__device__ float  g_y     [NROWS*DI];
__device__ float2 g_stats [NROWS];
__device__ float  g_xd    [NROWS*48];
__device__ float  g_E     [BB*CH*DI*DS];
__device__ float  g_Ssum  [BB*CH*DI];
__device__ float  g_hin   [BB*CH*DI*DS];

__device__ __forceinline__ float silu_f(float v){ return v / (1.f + __expf(-v)); }

__device__ __forceinline__ void cpa4(unsigned dst, const void* src){
    asm volatile("cp.async.ca.shared.global [%0], [%1], 4;\n" :: "r"(dst), "l"(src));
}
__device__ __forceinline__ void cpa8(unsigned dst, const void* src){
    asm volatile("cp.async.ca.shared.global [%0], [%1], 8;\n" :: "r"(dst), "l"(src));
}
__device__ __forceinline__ void cpa16(unsigned dst, const void* src){
    asm volatile("cp.async.ca.shared.global [%0], [%1], 16;\n" :: "r"(dst), "l"(src));
}
__device__ __forceinline__ void cp_commit(){ asm volatile("cp.async.commit_group;\n"); }
__device__ __forceinline__ void cp_wait1(){ asm volatile("cp.async.wait_group 1;\n"); }
__device__ __forceinline__ void cp_wait0(){ asm volatile("cp.async.wait_group 0;\n"); }

// ---- packed fp32x2 helpers ----
__device__ __forceinline__ void upk2(unsigned long long v, float& lo, float& hi){
    asm("mov.b64 {%0, %1}, %2;" : "=f"(lo), "=f"(hi) : "l"(v));
}
__device__ __forceinline__ void ffma2(unsigned long long& d,
        unsigned long long a, unsigned long long b){
    asm("fma.rn.f32x2 %0, %1, %2, %0;" : "+l"(d) : "l"(a), "l"(b));
}

#define AS_STRIDE 132
#define BS2_STRIDE 132   // duplicated-B rows: 128 floats used + pad

// =======================================================================
// gemm_in: BOTH input GEMMs, 128x64 tile, f32x2 inner loop with
// pre-packed operands (A pairs native; B duplicated in smem).
// =======================================================================
__global__ void __launch_bounds__(256) gemm_in_k(const float* __restrict__ x,
        const float* __restrict__ cond, const float* __restrict__ W_in,
        const float* __restrict__ W_con)
{
    __shared__ __align__(16) union {
        struct { float As[2][16*AS_STRIDE]; float Bs[2][16*BS2_STRIDE]; } s;
        float Ts[64*129];
    } u;

    const int K = DM;
    int tid = threadIdx.x;
    int tx = tid & 15, ty = tid >> 4;
    int n0 = blockIdx.x * 64;
    int m0 = blockIdx.y * 128;
    bool is_c = (n0 >= 2*DI);
    const float* A  = is_c ? cond  : x;
    const float* Bw = is_c ? W_con : W_in;
    int nb = is_c ? n0 - 2*DI : n0;

    int am  = tid >> 1;
    int akq = (tid & 1) * 8;
    int bn  = tid >> 2;          // 0..63
    int bkq = (tid & 3) * 4;
    const float* aP = A  + (size_t)(m0 + am) * K + akq;
    const float* bP = Bw + (size_t)(nb + bn) * K + bkq;

    unsigned long long acc2[4][4];
    #pragma unroll
    for (int i = 0; i < 4; i++)
        #pragma unroll
        for (int j = 0; j < 4; j++) acc2[i][j] = 0ULL;

    {
        float4 a0 = *(const float4*)(aP);
        float4 a1 = *(const float4*)(aP + 4);
        float4 b0 = *(const float4*)(bP);
        float* As = u.s.As[0]; float* Bs = u.s.Bs[0];
        As[(akq+0)*AS_STRIDE+am]=a0.x; As[(akq+1)*AS_STRIDE+am]=a0.y;
        As[(akq+2)*AS_STRIDE+am]=a0.z; As[(akq+3)*AS_STRIDE+am]=a0.w;
        As[(akq+4)*AS_STRIDE+am]=a1.x; As[(akq+5)*AS_STRIDE+am]=a1.y;
        As[(akq+6)*AS_STRIDE+am]=a1.z; As[(akq+7)*AS_STRIDE+am]=a1.w;
        *(float2*)&Bs[(bkq+0)*BS2_STRIDE + bn*2] = make_float2(b0.x, b0.x);
        *(float2*)&Bs[(bkq+1)*BS2_STRIDE + bn*2] = make_float2(b0.y, b0.y);
        *(float2*)&Bs[(bkq+2)*BS2_STRIDE + bn*2] = make_float2(b0.z, b0.z);
        *(float2*)&Bs[(bkq+3)*BS2_STRIDE + bn*2] = make_float2(b0.w, b0.w);
    }

    int buf = 0;
    const int nch = K / 16;
    for (int c = 0; c < nch; c++) {
        float4 na0, na1, nb0;
        if (c + 1 < nch) {
            na0 = *(const float4*)(aP + (c+1)*16);
            na1 = *(const float4*)(aP + (c+1)*16 + 4);
            nb0 = *(const float4*)(bP + (c+1)*16);
        }
        __syncthreads();
        const float* As = u.s.As[buf];
        const float* Bs = u.s.Bs[buf];
        #pragma unroll
        for (int kk = 0; kk < 16; kk++) {
            ulonglong2 a01 = *(const ulonglong2*)&As[kk*AS_STRIDE + ty*8];
            ulonglong2 a23 = *(const ulonglong2*)&As[kk*AS_STRIDE + ty*8 + 4];
            ulonglong2 b01 = *(const ulonglong2*)&Bs[kk*BS2_STRIDE + tx*8];
            ulonglong2 b23 = *(const ulonglong2*)&Bs[kk*BS2_STRIDE + tx*8 + 4];
            unsigned long long ap[4] = {a01.x, a01.y, a23.x, a23.y};
            unsigned long long bd[4] = {b01.x, b01.y, b23.x, b23.y};
            #pragma unroll
            for (int ip = 0; ip < 4; ip++)
                #pragma unroll
                for (int j = 0; j < 4; j++)
                    ffma2(acc2[ip][j], ap[ip], bd[j]);
        }
        if (c + 1 < nch) {
            float* Asw = u.s.As[buf^1]; float* Bsw = u.s.Bs[buf^1];
            Asw[(akq+0)*AS_STRIDE+am]=na0.x; Asw[(akq+1)*AS_STRIDE+am]=na0.y;
            Asw[(akq+2)*AS_STRIDE+am]=na0.z; Asw[(akq+3)*AS_STRIDE+am]=na0.w;
            Asw[(akq+4)*AS_STRIDE+am]=na1.x; Asw[(akq+5)*AS_STRIDE+am]=na1.y;
            Asw[(akq+6)*AS_STRIDE+am]=na1.z; Asw[(akq+7)*AS_STRIDE+am]=na1.w;
            *(float2*)&Bsw[(bkq+0)*BS2_STRIDE + bn*2] = make_float2(nb0.x, nb0.x);
            *(float2*)&Bsw[(bkq+1)*BS2_STRIDE + bn*2] = make_float2(nb0.y, nb0.y);
            *(float2*)&Bsw[(bkq+2)*BS2_STRIDE + bn*2] = make_float2(nb0.z, nb0.z);
            *(float2*)&Bsw[(bkq+3)*BS2_STRIDE + bn*2] = make_float2(nb0.w, nb0.w);
            buf ^= 1;
        }
    }

    float acc[8][4];
    #pragma unroll
    for (int ip = 0; ip < 4; ip++)
        #pragma unroll
        for (int j = 0; j < 4; j++)
            upk2(acc2[ip][j], acc[2*ip][j], acc[2*ip+1][j]);

    bool transp = is_c || (n0 < DI);
    if (transp) {
        __syncthreads();
        #pragma unroll
        for (int i = 0; i < 8; i++)
            #pragma unroll
            for (int j = 0; j < 4; j++)
                u.Ts[(tx*4+j)*129 + ty*8+i] = acc[i][j];
        __syncthreads();
        int b = m0 >> 12, l0 = m0 & 4095;
        float* dst = is_c ? g_c_pre : g_xa_pre;
        for (int e = tid; e < 64*128; e += 256) {
            int row = e >> 7, cc = e & 127;
            dst[((size_t)(b*DI + nb + row))*LL + l0 + cc] = u.Ts[row*129 + cc];
        }
    } else {
        #pragma unroll
        for (int i = 0; i < 8; i++) {
            int m = m0 + ty*8 + i;
            #pragma unroll
            for (int j = 0; j < 4; j++) {
                int nz = n0 - DI + tx*4 + j;
                g_z[(size_t)m*DI + nz] = silu_f(acc[i][j]);
            }
        }
    }
}

// =======================================================================
// gemm_out: out = LN(y)*z @ W_out^T, f32x2 inner loop, dup-B.
// =======================================================================
__global__ void __launch_bounds__(256) gemm_out_k(const float* __restrict__ Bw,
        const float* __restrict__ ln_w, const float* __restrict__ ln_b,
        float* __restrict__ out)
{
    __shared__ __align__(16) float As[2][16*AS_STRIDE];
    __shared__ __align__(16) float Bs[2][16*BS2_STRIDE];

    const int K = DI, N = DM;
    int tid = threadIdx.x;
    int tx = tid & 15, ty = tid >> 4;
    int n0 = blockIdx.x * 64;
    int m0 = blockIdx.y * 128;

    int am  = tid >> 1;
    int akq = (tid & 1) * 8;
    int bn  = tid >> 2;
    int bkq = (tid & 3) * 4;
    const float* yP = g_y + (size_t)(m0 + am) * K + akq;
    const float* zP = g_z + (size_t)(m0 + am) * K + akq;
    const float* bP = Bw  + (size_t)(n0 + bn) * K + bkq;
    float2 st = g_stats[m0 + am];

    unsigned long long acc2[4][4];
    #pragma unroll
    for (int i = 0; i < 4; i++)
        #pragma unroll
        for (int j = 0; j < 4; j++) acc2[i][j] = 0ULL;

    #define LOADA(c, r0, r1)                                                   \
    {                                                                          \
        int k = (c)*16;                                                        \
        float4 y0 = *(const float4*)(yP + k);                                  \
        float4 y1 = *(const float4*)(yP + k + 4);                              \
        float4 z0 = *(const float4*)(zP + k);                                  \
        float4 z1 = *(const float4*)(zP + k + 4);                              \
        float4 w0 = *(const float4*)(ln_w + k + akq);                          \
        float4 w1 = *(const float4*)(ln_w + k + akq + 4);                      \
        float4 lb0 = *(const float4*)(ln_b + k + akq);                         \
        float4 lb1 = *(const float4*)(ln_b + k + akq + 4);                     \
        r0.x = ((y0.x-st.x)*st.y*w0.x + lb0.x)*z0.x;                           \
        r0.y = ((y0.y-st.x)*st.y*w0.y + lb0.y)*z0.y;                           \
        r0.z = ((y0.z-st.x)*st.y*w0.z + lb0.z)*z0.z;                           \
        r0.w = ((y0.w-st.x)*st.y*w0.w + lb0.w)*z0.w;                           \
        r1.x = ((y1.x-st.x)*st.y*w1.x + lb1.x)*z1.x;                           \
        r1.y = ((y1.y-st.x)*st.y*w1.y + lb1.y)*z1.y;                           \
        r1.z = ((y1.z-st.x)*st.y*w1.z + lb1.z)*z1.z;                           \
        r1.w = ((y1.w-st.x)*st.y*w1.w + lb1.w)*z1.w;                           \
    }

    {
        float4 a0, a1;
        LOADA(0, a0, a1);
        float4 b0 = *(const float4*)(bP);
        As[0][(akq+0)*AS_STRIDE+am]=a0.x; As[0][(akq+1)*AS_STRIDE+am]=a0.y;
        As[0][(akq+2)*AS_STRIDE+am]=a0.z; As[0][(akq+3)*AS_STRIDE+am]=a0.w;
        As[0][(akq+4)*AS_STRIDE+am]=a1.x; As[0][(akq+5)*AS_STRIDE+am]=a1.y;
        As[0][(akq+6)*AS_STRIDE+am]=a1.z; As[0][(akq+7)*AS_STRIDE+am]=a1.w;
        *(float2*)&Bs[0][(bkq+0)*BS2_STRIDE + bn*2] = make_float2(b0.x, b0.x);
        *(float2*)&Bs[0][(bkq+1)*BS2_STRIDE + bn*2] = make_float2(b0.y, b0.y);
        *(float2*)&Bs[0][(bkq+2)*BS2_STRIDE + bn*2] = make_float2(b0.z, b0.z);
        *(float2*)&Bs[0][(bkq+3)*BS2_STRIDE + bn*2] = make_float2(b0.w, b0.w);
    }

    int buf = 0;
    const int nch = K / 16;
    for (int c = 0; c < nch; c++) {
        float4 na0, na1, nb0;
        if (c + 1 < nch) {
            LOADA(c+1, na0, na1);
            nb0 = *(const float4*)(bP + (c+1)*16);
        }
        __syncthreads();
        const float* Asr = As[buf];
        const float* Bsr = Bs[buf];
        #pragma unroll
        for (int kk = 0; kk < 16; kk++) {
            ulonglong2 a01 = *(const ulonglong2*)&Asr[kk*AS_STRIDE + ty*8];
            ulonglong2 a23 = *(const ulonglong2*)&Asr[kk*AS_STRIDE + ty*8 + 4];
            ulonglong2 b01 = *(const ulonglong2*)&Bsr[kk*BS2_STRIDE + tx*8];
            ulonglong2 b23 = *(const ulonglong2*)&Bsr[kk*BS2_STRIDE + tx*8 + 4];
            unsigned long long ap[4] = {a01.x, a01.y, a23.x, a23.y};
            unsigned long long bd[4] = {b01.x, b01.y, b23.x, b23.y};
            #pragma unroll
            for (int ip = 0; ip < 4; ip++)
                #pragma unroll
                for (int j = 0; j < 4; j++)
                    ffma2(acc2[ip][j], ap[ip], bd[j]);
        }
        if (c + 1 < nch) {
            float* Asw = As[buf^1]; float* Bsw = Bs[buf^1];
            Asw[(akq+0)*AS_STRIDE+am]=na0.x; Asw[(akq+1)*AS_STRIDE+am]=na0.y;
            Asw[(akq+2)*AS_STRIDE+am]=na0.z; Asw[(akq+3)*AS_STRIDE+am]=na0.w;
            Asw[(akq+4)*AS_STRIDE+am]=na1.x; Asw[(akq+5)*AS_STRIDE+am]=na1.y;
            Asw[(akq+6)*AS_STRIDE+am]=na1.z; Asw[(akq+7)*AS_STRIDE+am]=na1.w;
            *(float2*)&Bsw[(bkq+0)*BS2_STRIDE + bn*2] = make_float2(nb0.x, nb0.x);
            *(float2*)&Bsw[(bkq+1)*BS2_STRIDE + bn*2] = make_float2(nb0.y, nb0.y);
            *(float2*)&Bsw[(bkq+2)*BS2_STRIDE + bn*2] = make_float2(nb0.z, nb0.z);
            *(float2*)&Bsw[(bkq+3)*BS2_STRIDE + bn*2] = make_float2(nb0.w, nb0.w);
            buf ^= 1;
        }
    }
    #undef LOADA

    float acc[8][4];
    #pragma unroll
    for (int ip = 0; ip < 4; ip++)
        #pragma unroll
        for (int j = 0; j < 4; j++)
            upk2(acc2[ip][j], acc[2*ip][j], acc[2*ip+1][j]);

    #pragma unroll
    for (int i = 0; i < 8; i++) {
        int m = m0 + ty*8 + i;
        #pragma unroll
        for (int j = 0; j < 4; j++) {
            int n = n0 + tx*4 + j;
            out[(size_t)m*N + n] = acc[i][j];
        }
    }
}

// =======================================================================
// per-row LN stats
// =======================================================================
__global__ void __launch_bounds__(256) ln_stats_k()
{
    int row = blockIdx.x * 8 + (threadIdx.x >> 5);
    int lane = threadIdx.x & 31;
    const float* yr = g_y + (size_t)row * DI;
    float s = 0.f, q = 0.f;
    #pragma unroll
    for (int i = 0; i < 12; i++) {
        float v = yr[lane + 32*i];
        s += v; q += v*v;
    }
    #pragma unroll
    for (int o = 16; o > 0; o >>= 1) {
        s += __shfl_xor_sync(0xFFFFFFFFu, s, o);
        q += __shfl_xor_sync(0xFFFFFFFFu, q, o);
    }
    if (lane == 0) {
        float mu = s * (1.f / DI);
        float var = q * (1.f / DI) - mu*mu;
        g_stats[row] = make_float2(mu, rsqrtf(var + 1e-5f));
    }
}

// =======================================================================
// depthwise conv 3x3 + bias + silu for BOTH tensors
// =======================================================================
__global__ void __launch_bounds__(256) dwconv_k(const float* __restrict__ conv_w,
        const float* __restrict__ conv_b, const float* __restrict__ con_w,
        const float* __restrict__ con_b)
{
    __shared__ __align__(16) float imx[LL];
    __shared__ __align__(16) float imc[LL];
    int bd = blockIdx.x;
    int d  = bd % DI;
    const float* inx = g_xa_pre + (size_t)bd * LL;
    const float* inc = g_c_pre  + (size_t)bd * LL;
    float* outx = g_xa_conv + (size_t)bd * LL;
    float* outs = g_s       + (size_t)bd * LL;
    const float* wxp = conv_w + d * 9;
    const float* wcp = con_w  + d * 9;
    float bx = conv_b[d], bc = con_b[d];

    #pragma unroll
    for (int i = 0; i < 4; i++) {
        *(float4*)&imx[(threadIdx.x + 256*i)*4] = *(const float4*)&inx[(threadIdx.x + 256*i)*4];
        *(float4*)&imc[(threadIdx.x + 256*i)*4] = *(const float4*)&inc[(threadIdx.x + 256*i)*4];
    }
    float wx[9], wc[9];
    #pragma unroll
    for (int i = 0; i < 9; i++) { wx[i] = wxp[i]; wc[i] = wcp[i]; }
    __syncthreads();

    #pragma unroll
    for (int i = 0; i < 16; i++) {
        int l = threadIdx.x + 256*i;
        int y = l >> 6, x = l & 63;
        bool yl = y > 0, yh = y < 63, xl = x > 0, xh = x < 63;
        float ax = bx, ac = bc;
        if (yl) {
            if (xl) { ax = fmaf(imx[l-65], wx[0], ax); ac = fmaf(imc[l-65], wc[0], ac); }
            ax = fmaf(imx[l-64], wx[1], ax); ac = fmaf(imc[l-64], wc[1], ac);
            if (xh) { ax = fmaf(imx[l-63], wx[2], ax); ac = fmaf(imc[l-63], wc[2], ac); }
        }
        if (xl) { ax = fmaf(imx[l-1], wx[3], ax); ac = fmaf(imc[l-1], wc[3], ac); }
        ax = fmaf(imx[l], wx[4], ax); ac = fmaf(imc[l], wc[4], ac);
        if (xh) { ax = fmaf(imx[l+1], wx[5], ax); ac = fmaf(imc[l+1], wc[5], ac); }
        if (yh) {
            if (xl) { ax = fmaf(imx[l+63], wx[6], ax); ac = fmaf(imc[l+63], wc[6], ac); }
            ax = fmaf(imx[l+64], wx[7], ax); ac = fmaf(imc[l+64], wc[7], ac);
            if (xh) { ax = fmaf(imx[l+65], wx[8], ax); ac = fmaf(imc[l+65], wc[8], ac); }
        }
        float sa = silu_f(ax);
        outx[l] = sa;
        outs[l] = sa + silu_f(ac);
    }
}

// =======================================================================
// proj1: 64 px/block, x_proj GEMM (3-stage cp.async), write xd + B/C.
// =======================================================================
__global__ void __launch_bounds__(256) proj1_k(const float* __restrict__ x_proj_w,
        const int* __restrict__ rev_scan)
{
    __shared__ float xd[64*49];
    __shared__ __align__(16) struct { float sS[3][16*68]; float sB[3][16*48]; } a;

    int tid = threadIdx.x;
    int b   = blockIdx.x >> 6;
    int l0  = (blockIdx.x & 63) * 64;

    for (int e = tid; e < 3*16*48; e += 256) (&a.sB[0][0])[e] = 0.f;

    unsigned sS_b = (unsigned)__cvta_generic_to_shared(&a.sS[0][0]);
    unsigned sB_b = (unsigned)__cvta_generic_to_shared(&a.sB[0][0]);

    #define S1_PREFETCH(kc, bf)                                                \
    {                                                                          \
        int k = tid >> 4, px4 = tid & 15;                                      \
        cpa16(sS_b + (unsigned)(((bf)*16*68 + k*68 + px4*4)*4),                \
              g_s + ((size_t)(b*DI + (kc)*16 + k))*LL + l0 + px4*4);           \
        _Pragma("unroll")                                                      \
        for (int i = 0; i < 3; i++) {                                          \
            int e = tid + 256*i;                                               \
            int cc = e >> 4, kk = e & 15;                                      \
            if (cc < DR + 2*DS)                                                \
                cpa4(sB_b + (unsigned)(((bf)*16*48 + kk*48 + cc)*4),           \
                     x_proj_w + (size_t)cc*DI + (kc)*16 + kk);                 \
        }                                                                      \
    }

    __syncthreads();

    S1_PREFETCH(0, 0); cp_commit();
    S1_PREFETCH(1, 1); cp_commit();

    int tm = tid & 15, tn = tid >> 4;
    float acc[4][3];
    #pragma unroll
    for (int i = 0; i < 4; i++)
        #pragma unroll
        for (int j = 0; j < 3; j++) acc[i][j] = 0.f;

    const int NC1 = DI/16;
    for (int kc = 0; kc < NC1; kc++) {
        if (kc < NC1-1) cp_wait1(); else cp_wait0();
        __syncthreads();
        if (kc + 2 < NC1) { S1_PREFETCH(kc+2, (kc+2)%3); cp_commit(); }
        const float* sS = a.sS[kc%3];
        const float* sB = a.sB[kc%3];
        #pragma unroll
        for (int k = 0; k < 16; k++) {
            float4 av = *(const float4*)&sS[k*68 + tm*4];
            float b0 = sB[k*48 + tn*3 + 0];
            float b1 = sB[k*48 + tn*3 + 1];
            float b2 = sB[k*48 + tn*3 + 2];
            float ar[4] = {av.x, av.y, av.z, av.w};
            #pragma unroll
            for (int i = 0; i < 4; i++) {
                acc[i][0] = fmaf(ar[i], b0, acc[i][0]);
                acc[i][1] = fmaf(ar[i], b1, acc[i][1]);
                acc[i][2] = fmaf(ar[i], b2, acc[i][2]);
            }
        }
    }
    #pragma unroll
    for (int i = 0; i < 4; i++)
        #pragma unroll
        for (int j = 0; j < 3; j++)
            xd[(tm*4+i)*49 + tn*3+j] = acc[i][j];
    __syncthreads();

    for (int e = tid; e < 64*48; e += 256) {
        int row = e / 48, cc = e % 48;
        g_xd[((size_t)(b*LL) + l0 + row)*48 + cc] = xd[row*49 + cc];
    }

    int w = tid >> 5, lane = tid & 31;
    #pragma unroll
    for (int p = 0; p < 4; p++) {
        int px = w*8 + p*2 + (lane >> 4);
        int n  = lane & 15;
        int j  = __ldg(&rev_scan[l0 + px]);
        g_bc[((size_t)b*LL + j)*DS + n] =
            make_float2(xd[px*49 + DR + n], xd[px*49 + DR + DS + n]);
    }
    #undef S1_PREFETCH
}

// =======================================================================
// proj2: dt_proj + softplus + (delta,u) scatter. 512 blocks.
// =======================================================================
__global__ void __launch_bounds__(256) proj2_k(const float* __restrict__ dt_proj_w,
        const float* __restrict__ dt_proj_b, const int* __restrict__ rev_scan)
{
    __shared__ float sxd[32*13];
    __shared__ __align__(16) float xaT[3][32*36];

    int blk = blockIdx.x;
    int dh = blk & 1;
    int lt = (blk >> 1) & 127;
    int b  = blk >> 8;
    int l0 = lt * 32;
    int d0h = dh * 192;
    int tid = threadIdx.x, w = tid >> 5, lane = tid & 31;

    unsigned xa_b = (unsigned)__cvta_generic_to_shared(&xaT[0][0]);

    #define P2_PRE(cc, bf)                                                     \
    {                                                                          \
        int dd = tid >> 3, px4 = tid & 7;                                      \
        cpa16(xa_b + (unsigned)(((bf)*32*36 + dd*36 + px4*4)*4),               \
              g_xa_conv + ((size_t)(b*DI + d0h + (cc)*32 + dd))*LL + l0 + px4*4); \
    }

    P2_PRE(0, 0); cp_commit();
    P2_PRE(1, 1); cp_commit();

    for (int e = tid; e < 32*12; e += 256) {
        int row = e / 12, r = e % 12;
        sxd[row*13 + r] = g_xd[((size_t)(b*LL) + l0 + row)*48 + r];
    }

    const int NC2 = 6;
    for (int c = 0; c < NC2; c++) {
        if (c < NC2-1) cp_wait1(); else cp_wait0();
        __syncthreads();
        if (c + 2 < NC2) { P2_PRE(c+2, (c+2)%3); cp_commit(); }
        int d = d0h + c*32 + lane;
        float wr[DR];
        #pragma unroll
        for (int r = 0; r < DR; r++) wr[r] = __ldg(&dt_proj_w[(size_t)d*DR + r]);
        float bias = __ldg(&dt_proj_b[d]);
        const float* xa = xaT[c%3];
        #pragma unroll
        for (int p = 0; p < 4; p++) {
            int px = w*4 + p;
            float aa = bias;
            #pragma unroll
            for (int r = 0; r < DR; r++) aa = fmaf(wr[r], sxd[px*13 + r], aa);
            float delta = (aa > 20.f) ? aa : log1pf(__expf(aa));
            float uval  = xa[lane*36 + px];
            int j = __ldg(&rev_scan[l0 + px]);
            g_du[((size_t)b*LL + j)*DI + d] = make_float2(delta, uval);
        }
    }
    #undef P2_PRE
}

// =======================================================================
// scan pass 1: per-chunk end-state from h=0.
// =======================================================================
__global__ void __launch_bounds__(128) scan_p1_k(const float* __restrict__ A_logs)
{
    __shared__ __align__(16) float2 du2[3][TSTEP][8];
    __shared__ __align__(16) float2 bc2[3][TSTEP][DS];

    int blk = blockIdx.x;
    int k  = blk % (CH-1);
    int cb = blk / (CH-1);
    int b  = cb / 48;
    int d0 = (cb % 48) * 8;
    int tid = threadIdx.x;
    int wid = tid >> 5, lane = tid & 31;
    int g = lane >> 4, n = lane & 15;
    int ch = wid*2 + g;
    int d = d0 + ch;

    float a_coef = -__expf(A_logs[d*DS + n]);

    unsigned du_sm = (unsigned)__cvta_generic_to_shared(&du2[0][0][0]);
    unsigned bc_sm = (unsigned)__cvta_generic_to_shared(&bc2[0][0][0]);
    const float2* du_g = g_du + ((size_t)b*LL + k*CL)*DI + d0;
    const float2* bc_g = g_bc + ((size_t)b*LL + k*CL)*DS;

    #define P1_PRE(T, bf)                                                      \
    {                                                                          \
        _Pragma("unroll")                                                      \
        for (int i = 0; i < 2; i++) {                                          \
            int e = tid + 128*i;                                               \
            int jj = e >> 3, c = e & 7;                                        \
            cpa8(du_sm + (unsigned)((((bf)*TSTEP + jj)*8 + c)*8),              \
                 du_g + (size_t)((T)*TSTEP + jj)*DI + c);                      \
        }                                                                      \
        _Pragma("unroll")                                                      \
        for (int i = 0; i < 2; i++) {                                          \
            int e = tid + 128*i;                                               \
            int jj = e >> 3, q = e & 7;                                        \
            cpa16(bc_sm + (unsigned)((((bf)*TSTEP + jj)*DS + q*2)*8),          \
                  bc_g + (size_t)((T)*TSTEP + jj)*DS + q*2);                   \
        }                                                                      \
    }

    P1_PRE(0, 0); cp_commit();
    P1_PRE(1, 1); cp_commit();

    float h = 0.f, Ssum = 0.f;
    for (int T = 0; T < PTILES; T++) {
        if (T < PTILES-1) cp_wait1(); else cp_wait0();
        __syncthreads();
        if (T + 2 < PTILES) { P1_PRE(T+2, (T+2)%3); cp_commit(); }
        int bf = T % 3;
        #pragma unroll
        for (int jj = 0; jj < TSTEP; jj++) {
            float2 du = du2[bf][jj][ch];
            float2 bc = bc2[bf][jj][n];
            float dA = __expf(du.x * a_coef);
            h = fmaf(dA, h, du.x * du.y * bc.x);
            Ssum += du.x;
        }
    }
    #undef P1_PRE

    g_E[((size_t)(b*CH + k)*DI + d)*DS + n] = h;
    if (n == 0) g_Ssum[(size_t)(b*CH + k)*DI + d] = Ssum;
}

// =======================================================================
// scan pass 2: compose chunk carries
// =======================================================================
__global__ void __launch_bounds__(256) scan_p2_k(const float* __restrict__ A_logs)
{
    int t = blockIdx.x * 256 + threadIdx.x;
    int n  = t & 15;
    int dd = (t >> 4) % DI;
    int b  = t / (DI*DS);
    float a_coef = -__expf(A_logs[dd*DS + n]);
    float H = 0.f;
    for (int k = 0; k < CH; k++) {
        g_hin[((size_t)(b*CH + k)*DI + dd)*DS + n] = H;
        if (k < CH-1) {
            float S = g_Ssum[(size_t)(b*CH + k)*DI + dd];
            float E = g_E[((size_t)(b*CH + k)*DI + dd)*DS + n];
            H = fmaf(__expf(a_coef * S), H, E);
        }
    }
}

// =======================================================================
// scan pass 3: full scan within chunk, seeded, outputs y
// =======================================================================
__global__ void __launch_bounds__(128) scan_p3_k(const float* __restrict__ A_logs,
        const float* __restrict__ Ds, const int* __restrict__ scan_path)
{
    __shared__ __align__(16) float2 du2[2][TSTEP][8];
    __shared__ __align__(16) float2 bc2[2][TSTEP][DS];
    __shared__ float  ps[TSTEP*8*17];
    __shared__ float  s_D[8];

    int blk = blockIdx.x;
    int k  = blk % CH;
    int cb = blk / CH;
    int b  = cb / 48;
    int d0 = (cb % 48) * 8;
    int tid = threadIdx.x;
    int wid = tid >> 5, lane = tid & 31;
    int g = lane >> 4, n = lane & 15;
    int ch = wid*2 + g;
    int d = d0 + ch;

    float a_coef = -__expf(A_logs[d*DS + n]);
    if (tid < 8) s_D[tid] = Ds[d0 + tid];

    unsigned du_sm = (unsigned)__cvta_generic_to_shared(&du2[0][0][0]);
    unsigned bc_sm = (unsigned)__cvta_generic_to_shared(&bc2[0][0][0]);
    const float2* du_g = g_du + ((size_t)b*LL + k*CL)*DI + d0;
    const float2* bc_g = g_bc + ((size_t)b*LL + k*CL)*DS;

    {
        #pragma unroll
        for (int i = 0; i < 2; i++) {
            int e = tid + 128*i;
            int jj = e >> 3, c = e & 7;
            cpa8(du_sm + (unsigned)((jj*8 + c)*8), du_g + (size_t)jj*DI + c);
        }
        #pragma unroll
        for (int i = 0; i < 2; i++) {
            int e = tid + 128*i;
            int jj = e >> 3, q = e & 7;
            cpa16(bc_sm + (unsigned)((jj*DS + q*2)*8), bc_g + (size_t)jj*DS + q*2);
        }
        cp_commit();
    }

    float h = g_hin[((size_t)(b*CH + k)*DI + d)*DS + n];
    int buf = 0;
    for (int T = 0; T < PTILES; T++) {
        if (T + 1 < PTILES) {
            int o = (buf^1) * TSTEP;
            #pragma unroll
            for (int i = 0; i < 2; i++) {
                int e = tid + 128*i;
                int jj = e >> 3, c = e & 7;
                cpa8(du_sm + (unsigned)(((o+jj)*8 + c)*8),
                     du_g + (size_t)((T+1)*TSTEP + jj)*DI + c);
            }
            #pragma unroll
            for (int i = 0; i < 2; i++) {
                int e = tid + 128*i;
                int jj = e >> 3, q = e & 7;
                cpa16(bc_sm + (unsigned)(((o+jj)*DS + q*2)*8),
                      bc_g + (size_t)((T+1)*TSTEP + jj)*DS + q*2);
            }
            cp_commit();
            cp_wait1();
        } else {
            cp_wait0();
        }
        __syncthreads();

        #pragma unroll 8
        for (int jj = 0; jj < TSTEP; jj++) {
            float2 du = du2[buf][jj][ch];
            float2 bc = bc2[buf][jj][n];
            float dA = __expf(du.x * a_coef);
            h = fmaf(dA, h, du.x * du.y * bc.x);
            ps[(jj*8 + ch)*17 + n] = h * bc.y;
        }
        __syncthreads();

        #pragma unroll
        for (int i = 0; i < 2; i++) {
            int e = tid + 128*i;
            int jj = e >> 3, c = e & 7;
            const float* p = &ps[(jj*8 + c)*17];
            float sum = p[0];
            #pragma unroll
            for (int kk = 1; kk < DS; kk++) sum += p[kk];
            float uval = du2[buf][jj][c].y;
            int pos = __ldg(&scan_path[k*CL + T*TSTEP + jj]);
            g_y[((size_t)b*LL + pos)*DI + d0 + c] = fmaf(uval, s_D[c], sum);
        }
        buf ^= 1;
    }
}

// ---------------- launch ----------------
extern "C" void kernel_launch(void* const* d_in, const int* in_sizes, int n_in,
                              void* d_out, int out_size)
{
    const float* x          = (const float*)d_in[0];
    const float* cond       = (const float*)d_in[1];
    const float* W_in       = (const float*)d_in[2];
    const float* W_con      = (const float*)d_in[3];
    const float* conv_w     = (const float*)d_in[4];
    const float* conv_b     = (const float*)d_in[5];
    const float* con_conv_w = (const float*)d_in[6];
    const float* con_conv_b = (const float*)d_in[7];
    const float* x_proj_w   = (const float*)d_in[8];
    const float* dt_proj_w  = (const float*)d_in[9];
    const float* dt_proj_b  = (const float*)d_in[10];
    const float* A_logs     = (const float*)d_in[11];
    const float* Ds         = (const float*)d_in[12];
    const float* ln_w       = (const float*)d_in[13];
    const float* ln_b       = (const float*)d_in[14];
    const float* W_out      = (const float*)d_in[15];
    const int*   scan_path  = (const int*)d_in[16];
    const int*   rev_scan   = (const int*)d_in[17];
    float* out = (float*)d_out;

    gemm_in_k<<<dim3(3*DI/64, NROWS/128), 256>>>(x, cond, W_in, W_con);
    dwconv_k<<<BB*DI, 256>>>(conv_w, conv_b, con_conv_w, con_conv_b);
    proj1_k<<<NROWS/64, 256>>>(x_proj_w, rev_scan);
    proj2_k<<<512, 256>>>(dt_proj_w, dt_proj_b, rev_scan);
    scan_p1_k<<<96*(CH-1), 128>>>(A_logs);
    scan_p2_k<<<(BB*DI*DS)/256, 256>>>(A_logs);
    scan_p3_k<<<96*CH, 128>>>(A_logs, Ds, scan_path);
    ln_stats_k<<<NROWS/8, 256>>>();
    gemm_out_k<<<dim3(DM/64, NROWS/128), 256>>>(W_out, ln_w, ln_b, out);
}

// round 12
// speedup vs baseline: 1.3581x; 1.3581x over previous
#include <cuda_runtime.h>

#define BB 2
#define DM 192
#define DI 384
#define DS 16
#define DR 12
#define HH 64
#define WW 64
#define LL 4096
#define NROWS (BB*LL)   // 8192

#define TSTEP 32
#define CH 32
#define CL (LL/CH)          // 128 steps per chunk
#define PTILES (CL/TSTEP)   // 4 tiles per chunk

// ---------------- scratch ----------------
__device__ float  g_xa_pre[BB*DI*LL];
__device__ float  g_c_pre [BB*DI*LL];
__device__ float  g_xa_conv[BB*DI*LL];
__device__ float  g_s     [BB*DI*LL];
__device__ float  g_z     [NROWS*DI];
__device__ float2 g_du    [BB*LL*DI];
__device__ float2 g_bc    [BB*LL*DS];
__device__ float  g_y     [NROWS*DI];
__device__ float2 g_stats [NROWS];
__device__ float  g_xd    [NROWS*48];
__device__ float  g_E     [BB*CH*DI*DS];
__device__ float  g_Ssum  [BB*CH*DI];
__device__ float  g_hin   [BB*CH*DI*DS];

__device__ __forceinline__ float silu_f(float v){ return v / (1.f + __expf(-v)); }

__device__ __forceinline__ void cpa4(unsigned dst, const void* src){
    asm volatile("cp.async.ca.shared.global [%0], [%1], 4;\n" :: "r"(dst), "l"(src));
}
__device__ __forceinline__ void cpa8(unsigned dst, const void* src){
    asm volatile("cp.async.ca.shared.global [%0], [%1], 8;\n" :: "r"(dst), "l"(src));
}
__device__ __forceinline__ void cpa16(unsigned dst, const void* src){
    asm volatile("cp.async.ca.shared.global [%0], [%1], 16;\n" :: "r"(dst), "l"(src));
}
__device__ __forceinline__ void cp_commit(){ asm volatile("cp.async.commit_group;\n"); }
__device__ __forceinline__ void cp_wait1(){ asm volatile("cp.async.wait_group 1;\n"); }
__device__ __forceinline__ void cp_wait0(){ asm volatile("cp.async.wait_group 0;\n"); }

#define AS_STRIDE 132
#define BS_STRIDE 68

// =======================================================================
// gemm_in: BOTH input GEMMs in one launch. 128x64 tile, 8x4 micro,
// scalar FFMA (proven fastest), single __syncthreads per K-chunk.
// =======================================================================
__global__ void __launch_bounds__(256) gemm_in_k(const float* __restrict__ x,
        const float* __restrict__ cond, const float* __restrict__ W_in,
        const float* __restrict__ W_con)
{
    __shared__ __align__(16) union {
        struct { float As[2][16*AS_STRIDE]; float Bs[2][16*BS_STRIDE]; } s;
        float Ts[64*129];
    } u;

    const int K = DM;
    int tid = threadIdx.x;
    int tx = tid & 15, ty = tid >> 4;
    int n0 = blockIdx.x * 64;
    int m0 = blockIdx.y * 128;
    bool is_c = (n0 >= 2*DI);
    const float* A  = is_c ? cond  : x;
    const float* Bw = is_c ? W_con : W_in;
    int nb = is_c ? n0 - 2*DI : n0;

    int am  = tid >> 1;
    int akq = (tid & 1) * 8;
    int bn  = tid >> 2;
    int bkq = (tid & 3) * 4;
    const float* aP = A  + (size_t)(m0 + am) * K + akq;
    const float* bP = Bw + (size_t)(nb + bn) * K + bkq;

    float acc[8][4];
    #pragma unroll
    for (int i = 0; i < 8; i++)
        #pragma unroll
        for (int j = 0; j < 4; j++) acc[i][j] = 0.f;

    {
        float4 a0 = *(const float4*)(aP);
        float4 a1 = *(const float4*)(aP + 4);
        float4 b0 = *(const float4*)(bP);
        float* As = u.s.As[0]; float* Bs = u.s.Bs[0];
        As[(akq+0)*AS_STRIDE+am]=a0.x; As[(akq+1)*AS_STRIDE+am]=a0.y;
        As[(akq+2)*AS_STRIDE+am]=a0.z; As[(akq+3)*AS_STRIDE+am]=a0.w;
        As[(akq+4)*AS_STRIDE+am]=a1.x; As[(akq+5)*AS_STRIDE+am]=a1.y;
        As[(akq+6)*AS_STRIDE+am]=a1.z; As[(akq+7)*AS_STRIDE+am]=a1.w;
        Bs[(bkq+0)*BS_STRIDE+bn]=b0.x; Bs[(bkq+1)*BS_STRIDE+bn]=b0.y;
        Bs[(bkq+2)*BS_STRIDE+bn]=b0.z; Bs[(bkq+3)*BS_STRIDE+bn]=b0.w;
    }

    int buf = 0;
    const int nch = K / 16;
    for (int c = 0; c < nch; c++) {
        float4 na0, na1, nb0;
        if (c + 1 < nch) {
            na0 = *(const float4*)(aP + (c+1)*16);
            na1 = *(const float4*)(aP + (c+1)*16 + 4);
            nb0 = *(const float4*)(bP + (c+1)*16);
        }
        __syncthreads();
        const float* As = u.s.As[buf];
        const float* Bs = u.s.Bs[buf];
        #pragma unroll
        for (int kk = 0; kk < 16; kk++) {
            float4 a0 = *(const float4*)&As[kk*AS_STRIDE + ty*8];
            float4 a1 = *(const float4*)&As[kk*AS_STRIDE + ty*8 + 4];
            float4 b0 = *(const float4*)&Bs[kk*BS_STRIDE + tx*4];
            float ar[8] = {a0.x,a0.y,a0.z,a0.w,a1.x,a1.y,a1.z,a1.w};
            float br[4] = {b0.x,b0.y,b0.z,b0.w};
            #pragma unroll
            for (int i = 0; i < 8; i++)
                #pragma unroll
                for (int j = 0; j < 4; j++)
                    acc[i][j] = fmaf(ar[i], br[j], acc[i][j]);
        }
        if (c + 1 < nch) {
            float* Asw = u.s.As[buf^1]; float* Bsw = u.s.Bs[buf^1];
            Asw[(akq+0)*AS_STRIDE+am]=na0.x; Asw[(akq+1)*AS_STRIDE+am]=na0.y;
            Asw[(akq+2)*AS_STRIDE+am]=na0.z; Asw[(akq+3)*AS_STRIDE+am]=na0.w;
            Asw[(akq+4)*AS_STRIDE+am]=na1.x; Asw[(akq+5)*AS_STRIDE+am]=na1.y;
            Asw[(akq+6)*AS_STRIDE+am]=na1.z; Asw[(akq+7)*AS_STRIDE+am]=na1.w;
            Bsw[(bkq+0)*BS_STRIDE+bn]=nb0.x; Bsw[(bkq+1)*BS_STRIDE+bn]=nb0.y;
            Bsw[(bkq+2)*BS_STRIDE+bn]=nb0.z; Bsw[(bkq+3)*BS_STRIDE+bn]=nb0.w;
            buf ^= 1;
        }
    }

    bool transp = is_c || (n0 < DI);
    if (transp) {
        __syncthreads();
        #pragma unroll
        for (int i = 0; i < 8; i++)
            #pragma unroll
            for (int j = 0; j < 4; j++)
                u.Ts[(tx*4+j)*129 + ty*8+i] = acc[i][j];
        __syncthreads();
        int b = m0 >> 12, l0 = m0 & 4095;
        float* dst = is_c ? g_c_pre : g_xa_pre;
        for (int e = tid; e < 64*128; e += 256) {
            int row = e >> 7, cc = e & 127;
            dst[((size_t)(b*DI + nb + row))*LL + l0 + cc] = u.Ts[row*129 + cc];
        }
    } else {
        #pragma unroll
        for (int i = 0; i < 8; i++) {
            int m = m0 + ty*8 + i;
            #pragma unroll
            for (int j = 0; j < 4; j++) {
                int nz = n0 - DI + tx*4 + j;
                g_z[(size_t)m*DI + nz] = silu_f(acc[i][j]);
            }
        }
    }
}

// =======================================================================
// gemm_out: out = LN(y)*z @ W_out^T, LN applied on the fly, scalar FFMA.
// =======================================================================
__global__ void __launch_bounds__(256) gemm_out_k(const float* __restrict__ Bw,
        const float* __restrict__ ln_w, const float* __restrict__ ln_b,
        float* __restrict__ out)
{
    __shared__ __align__(16) float As[2][16*AS_STRIDE];
    __shared__ __align__(16) float Bs[2][16*BS_STRIDE];

    const int K = DI, N = DM;
    int tid = threadIdx.x;
    int tx = tid & 15, ty = tid >> 4;
    int n0 = blockIdx.x * 64;
    int m0 = blockIdx.y * 128;

    int am  = tid >> 1;
    int akq = (tid & 1) * 8;
    int bn  = tid >> 2;
    int bkq = (tid & 3) * 4;
    const float* yP = g_y + (size_t)(m0 + am) * K + akq;
    const float* zP = g_z + (size_t)(m0 + am) * K + akq;
    const float* bP = Bw  + (size_t)(n0 + bn) * K + bkq;
    float2 st = g_stats[m0 + am];

    float acc[8][4];
    #pragma unroll
    for (int i = 0; i < 8; i++)
        #pragma unroll
        for (int j = 0; j < 4; j++) acc[i][j] = 0.f;

    #define LOADA(c, r0, r1)                                                   \
    {                                                                          \
        int k = (c)*16;                                                        \
        float4 y0 = *(const float4*)(yP + k);                                  \
        float4 y1 = *(const float4*)(yP + k + 4);                              \
        float4 z0 = *(const float4*)(zP + k);                                  \
        float4 z1 = *(const float4*)(zP + k + 4);                              \
        float4 w0 = *(const float4*)(ln_w + k + akq);                          \
        float4 w1 = *(const float4*)(ln_w + k + akq + 4);                      \
        float4 lb0 = *(const float4*)(ln_b + k + akq);                         \
        float4 lb1 = *(const float4*)(ln_b + k + akq + 4);                     \
        r0.x = ((y0.x-st.x)*st.y*w0.x + lb0.x)*z0.x;                           \
        r0.y = ((y0.y-st.x)*st.y*w0.y + lb0.y)*z0.y;                           \
        r0.z = ((y0.z-st.x)*st.y*w0.z + lb0.z)*z0.z;                           \
        r0.w = ((y0.w-st.x)*st.y*w0.w + lb0.w)*z0.w;                           \
        r1.x = ((y1.x-st.x)*st.y*w1.x + lb1.x)*z1.x;                           \
        r1.y = ((y1.y-st.x)*st.y*w1.y + lb1.y)*z1.y;                           \
        r1.z = ((y1.z-st.x)*st.y*w1.z + lb1.z)*z1.z;                           \
        r1.w = ((y1.w-st.x)*st.y*w1.w + lb1.w)*z1.w;                           \
    }

    {
        float4 a0, a1;
        LOADA(0, a0, a1);
        float4 b0 = *(const float4*)(bP);
        As[0][(akq+0)*AS_STRIDE+am]=a0.x; As[0][(akq+1)*AS_STRIDE+am]=a0.y;
        As[0][(akq+2)*AS_STRIDE+am]=a0.z; As[0][(akq+3)*AS_STRIDE+am]=a0.w;
        As[0][(akq+4)*AS_STRIDE+am]=a1.x; As[0][(akq+5)*AS_STRIDE+am]=a1.y;
        As[0][(akq+6)*AS_STRIDE+am]=a1.z; As[0][(akq+7)*AS_STRIDE+am]=a1.w;
        Bs[0][(bkq+0)*BS_STRIDE+bn]=b0.x; Bs[0][(bkq+1)*BS_STRIDE+bn]=b0.y;
        Bs[0][(bkq+2)*BS_STRIDE+bn]=b0.z; Bs[0][(bkq+3)*BS_STRIDE+bn]=b0.w;
    }

    int buf = 0;
    const int nch = K / 16;
    for (int c = 0; c < nch; c++) {
        float4 na0, na1, nb0;
        if (c + 1 < nch) {
            LOADA(c+1, na0, na1);
            nb0 = *(const float4*)(bP + (c+1)*16);
        }
        __syncthreads();
        const float* Asr = As[buf];
        const float* Bsr = Bs[buf];
        #pragma unroll
        for (int kk = 0; kk < 16; kk++) {
            float4 a0 = *(const float4*)&Asr[kk*AS_STRIDE + ty*8];
            float4 a1 = *(const float4*)&Asr[kk*AS_STRIDE + ty*8 + 4];
            float4 b0 = *(const float4*)&Bsr[kk*BS_STRIDE + tx*4];
            float ar[8] = {a0.x,a0.y,a0.z,a0.w,a1.x,a1.y,a1.z,a1.w};
            float br[4] = {b0.x,b0.y,b0.z,b0.w};
            #pragma unroll
            for (int i = 0; i < 8; i++)
                #pragma unroll
                for (int j = 0; j < 4; j++)
                    acc[i][j] = fmaf(ar[i], br[j], acc[i][j]);
        }
        if (c + 1 < nch) {
            float* Asw = As[buf^1]; float* Bsw = Bs[buf^1];
            Asw[(akq+0)*AS_STRIDE+am]=na0.x; Asw[(akq+1)*AS_STRIDE+am]=na0.y;
            Asw[(akq+2)*AS_STRIDE+am]=na0.z; Asw[(akq+3)*AS_STRIDE+am]=na0.w;
            Asw[(akq+4)*AS_STRIDE+am]=na1.x; Asw[(akq+5)*AS_STRIDE+am]=na1.y;
            Asw[(akq+6)*AS_STRIDE+am]=na1.z; Asw[(akq+7)*AS_STRIDE+am]=na1.w;
            Bsw[(bkq+0)*BS_STRIDE+bn]=nb0.x; Bsw[(bkq+1)*BS_STRIDE+bn]=nb0.y;
            Bsw[(bkq+2)*BS_STRIDE+bn]=nb0.z; Bsw[(bkq+3)*BS_STRIDE+bn]=nb0.w;
            buf ^= 1;
        }
    }
    #undef LOADA

    #pragma unroll
    for (int i = 0; i < 8; i++) {
        int m = m0 + ty*8 + i;
        #pragma unroll
        for (int j = 0; j < 4; j++) {
            int n = n0 + tx*4 + j;
            out[(size_t)m*N + n] = acc[i][j];
        }
    }
}

// =======================================================================
// per-row LN stats
// =======================================================================
__global__ void __launch_bounds__(256) ln_stats_k()
{
    int row = blockIdx.x * 8 + (threadIdx.x >> 5);
    int lane = threadIdx.x & 31;
    const float* yr = g_y + (size_t)row * DI;
    float s = 0.f, q = 0.f;
    #pragma unroll
    for (int i = 0; i < 12; i++) {
        float v = yr[lane + 32*i];
        s += v; q += v*v;
    }
    #pragma unroll
    for (int o = 16; o > 0; o >>= 1) {
        s += __shfl_xor_sync(0xFFFFFFFFu, s, o);
        q += __shfl_xor_sync(0xFFFFFFFFu, q, o);
    }
    if (lane == 0) {
        float mu = s * (1.f / DI);
        float var = q * (1.f / DI) - mu*mu;
        g_stats[row] = make_float2(mu, rsqrtf(var + 1e-5f));
    }
}

// =======================================================================
// depthwise conv 3x3 + bias + silu for BOTH tensors
// =======================================================================
__global__ void __launch_bounds__(256) dwconv_k(const float* __restrict__ conv_w,
        const float* __restrict__ conv_b, const float* __restrict__ con_w,
        const float* __restrict__ con_b)
{
    __shared__ __align__(16) float imx[LL];
    __shared__ __align__(16) float imc[LL];
    int bd = blockIdx.x;
    int d  = bd % DI;
    const float* inx = g_xa_pre + (size_t)bd * LL;
    const float* inc = g_c_pre  + (size_t)bd * LL;
    float* outx = g_xa_conv + (size_t)bd * LL;
    float* outs = g_s       + (size_t)bd * LL;
    const float* wxp = conv_w + d * 9;
    const float* wcp = con_w  + d * 9;
    float bx = conv_b[d], bc = con_b[d];

    #pragma unroll
    for (int i = 0; i < 4; i++) {
        *(float4*)&imx[(threadIdx.x + 256*i)*4] = *(const float4*)&inx[(threadIdx.x + 256*i)*4];
        *(float4*)&imc[(threadIdx.x + 256*i)*4] = *(const float4*)&inc[(threadIdx.x + 256*i)*4];
    }
    float wx[9], wc[9];
    #pragma unroll
    for (int i = 0; i < 9; i++) { wx[i] = wxp[i]; wc[i] = wcp[i]; }
    __syncthreads();

    #pragma unroll
    for (int i = 0; i < 16; i++) {
        int l = threadIdx.x + 256*i;
        int y = l >> 6, x = l & 63;
        bool yl = y > 0, yh = y < 63, xl = x > 0, xh = x < 63;
        float ax = bx, ac = bc;
        if (yl) {
            if (xl) { ax = fmaf(imx[l-65], wx[0], ax); ac = fmaf(imc[l-65], wc[0], ac); }
            ax = fmaf(imx[l-64], wx[1], ax); ac = fmaf(imc[l-64], wc[1], ac);
            if (xh) { ax = fmaf(imx[l-63], wx[2], ax); ac = fmaf(imc[l-63], wc[2], ac); }
        }
        if (xl) { ax = fmaf(imx[l-1], wx[3], ax); ac = fmaf(imc[l-1], wc[3], ac); }
        ax = fmaf(imx[l], wx[4], ax); ac = fmaf(imc[l], wc[4], ac);
        if (xh) { ax = fmaf(imx[l+1], wx[5], ax); ac = fmaf(imc[l+1], wc[5], ac); }
        if (yh) {
            if (xl) { ax = fmaf(imx[l+63], wx[6], ax); ac = fmaf(imc[l+63], wc[6], ac); }
            ax = fmaf(imx[l+64], wx[7], ax); ac = fmaf(imc[l+64], wc[7], ac);
            if (xh) { ax = fmaf(imx[l+65], wx[8], ax); ac = fmaf(imc[l+65], wc[8], ac); }
        }
        float sa = silu_f(ax);
        outx[l] = sa;
        outs[l] = sa + silu_f(ac);
    }
}

// =======================================================================
// proj1: 64 px/block, x_proj GEMM (3-stage cp.async), write xd + B/C.
// =======================================================================
__global__ void __launch_bounds__(256) proj1_k(const float* __restrict__ x_proj_w,
        const int* __restrict__ rev_scan)
{
    __shared__ float xd[64*49];
    __shared__ __align__(16) struct { float sS[3][16*68]; float sB[3][16*48]; } a;

    int tid = threadIdx.x;
    int b   = blockIdx.x >> 6;
    int l0  = (blockIdx.x & 63) * 64;

    for (int e = tid; e < 3*16*48; e += 256) (&a.sB[0][0])[e] = 0.f;

    unsigned sS_b = (unsigned)__cvta_generic_to_shared(&a.sS[0][0]);
    unsigned sB_b = (unsigned)__cvta_generic_to_shared(&a.sB[0][0]);

    #define S1_PREFETCH(kc, bf)                                                \
    {                                                                          \
        int k = tid >> 4, px4 = tid & 15;                                      \
        cpa16(sS_b + (unsigned)(((bf)*16*68 + k*68 + px4*4)*4),                \
              g_s + ((size_t)(b*DI + (kc)*16 + k))*LL + l0 + px4*4);           \
        _Pragma("unroll")                                                      \
        for (int i = 0; i < 3; i++) {                                          \
            int e = tid + 256*i;                                               \
            int cc = e >> 4, kk = e & 15;                                      \
            if (cc < DR + 2*DS)                                                \
                cpa4(sB_b + (unsigned)(((bf)*16*48 + kk*48 + cc)*4),           \
                     x_proj_w + (size_t)cc*DI + (kc)*16 + kk);                 \
        }                                                                      \
    }

    __syncthreads();

    S1_PREFETCH(0, 0); cp_commit();
    S1_PREFETCH(1, 1); cp_commit();

    int tm = tid & 15, tn = tid >> 4;
    float acc[4][3];
    #pragma unroll
    for (int i = 0; i < 4; i++)
        #pragma unroll
        for (int j = 0; j < 3; j++) acc[i][j] = 0.f;

    const int NC1 = DI/16;
    for (int kc = 0; kc < NC1; kc++) {
        if (kc < NC1-1) cp_wait1(); else cp_wait0();
        __syncthreads();
        if (kc + 2 < NC1) { S1_PREFETCH(kc+2, (kc+2)%3); cp_commit(); }
        const float* sS = a.sS[kc%3];
        const float* sB = a.sB[kc%3];
        #pragma unroll
        for (int k = 0; k < 16; k++) {
            float4 av = *(const float4*)&sS[k*68 + tm*4];
            float b0 = sB[k*48 + tn*3 + 0];
            float b1 = sB[k*48 + tn*3 + 1];
            float b2 = sB[k*48 + tn*3 + 2];
            float ar[4] = {av.x, av.y, av.z, av.w};
            #pragma unroll
            for (int i = 0; i < 4; i++) {
                acc[i][0] = fmaf(ar[i], b0, acc[i][0]);
                acc[i][1] = fmaf(ar[i], b1, acc[i][1]);
                acc[i][2] = fmaf(ar[i], b2, acc[i][2]);
            }
        }
    }
    #pragma unroll
    for (int i = 0; i < 4; i++)
        #pragma unroll
        for (int j = 0; j < 3; j++)
            xd[(tm*4+i)*49 + tn*3+j] = acc[i][j];
    __syncthreads();

    for (int e = tid; e < 64*48; e += 256) {
        int row = e / 48, cc = e % 48;
        g_xd[((size_t)(b*LL) + l0 + row)*48 + cc] = xd[row*49 + cc];
    }

    int w = tid >> 5, lane = tid & 31;
    #pragma unroll
    for (int p = 0; p < 4; p++) {
        int px = w*8 + p*2 + (lane >> 4);
        int n  = lane & 15;
        int j  = __ldg(&rev_scan[l0 + px]);
        g_bc[((size_t)b*LL + j)*DS + n] =
            make_float2(xd[px*49 + DR + n], xd[px*49 + DR + DS + n]);
    }
    #undef S1_PREFETCH
}

// =======================================================================
// proj2: dt_proj + softplus + (delta,u) scatter. 512 blocks.
// =======================================================================
__global__ void __launch_bounds__(256) proj2_k(const float* __restrict__ dt_proj_w,
        const float* __restrict__ dt_proj_b, const int* __restrict__ rev_scan)
{
    __shared__ float sxd[32*13];
    __shared__ __align__(16) float xaT[3][32*36];

    int blk = blockIdx.x;
    int dh = blk & 1;
    int lt = (blk >> 1) & 127;
    int b  = blk >> 8;
    int l0 = lt * 32;
    int d0h = dh * 192;
    int tid = threadIdx.x, w = tid >> 5, lane = tid & 31;

    unsigned xa_b = (unsigned)__cvta_generic_to_shared(&xaT[0][0]);

    #define P2_PRE(cc, bf)                                                     \
    {                                                                          \
        int dd = tid >> 3, px4 = tid & 7;                                      \
        cpa16(xa_b + (unsigned)(((bf)*32*36 + dd*36 + px4*4)*4),               \
              g_xa_conv + ((size_t)(b*DI + d0h + (cc)*32 + dd))*LL + l0 + px4*4); \
    }

    P2_PRE(0, 0); cp_commit();
    P2_PRE(1, 1); cp_commit();

    for (int e = tid; e < 32*12; e += 256) {
        int row = e / 12, r = e % 12;
        sxd[row*13 + r] = g_xd[((size_t)(b*LL) + l0 + row)*48 + r];
    }

    const int NC2 = 6;
    for (int c = 0; c < NC2; c++) {
        if (c < NC2-1) cp_wait1(); else cp_wait0();
        __syncthreads();
        if (c + 2 < NC2) { P2_PRE(c+2, (c+2)%3); cp_commit(); }
        int d = d0h + c*32 + lane;
        float wr[DR];
        #pragma unroll
        for (int r = 0; r < DR; r++) wr[r] = __ldg(&dt_proj_w[(size_t)d*DR + r]);
        float bias = __ldg(&dt_proj_b[d]);
        const float* xa = xaT[c%3];
        #pragma unroll
        for (int p = 0; p < 4; p++) {
            int px = w*4 + p;
            float aa = bias;
            #pragma unroll
            for (int r = 0; r < DR; r++) aa = fmaf(wr[r], sxd[px*13 + r], aa);
            float delta = (aa > 20.f) ? aa : log1pf(__expf(aa));
            float uval  = xa[lane*36 + px];
            int j = __ldg(&rev_scan[l0 + px]);
            g_du[((size_t)b*LL + j)*DI + d] = make_float2(delta, uval);
        }
    }
    #undef P2_PRE
}

// =======================================================================
// scan pass 1: per-chunk end-state from h=0.
// =======================================================================
__global__ void __launch_bounds__(128) scan_p1_k(const float* __restrict__ A_logs)
{
    __shared__ __align__(16) float2 du2[3][TSTEP][8];
    __shared__ __align__(16) float2 bc2[3][TSTEP][DS];

    int blk = blockIdx.x;
    int k  = blk % (CH-1);
    int cb = blk / (CH-1);
    int b  = cb / 48;
    int d0 = (cb % 48) * 8;
    int tid = threadIdx.x;
    int wid = tid >> 5, lane = tid & 31;
    int g = lane >> 4, n = lane & 15;
    int ch = wid*2 + g;
    int d = d0 + ch;

    float a_coef = -__expf(A_logs[d*DS + n]);

    unsigned du_sm = (unsigned)__cvta_generic_to_shared(&du2[0][0][0]);
    unsigned bc_sm = (unsigned)__cvta_generic_to_shared(&bc2[0][0][0]);
    const float2* du_g = g_du + ((size_t)b*LL + k*CL)*DI + d0;
    const float2* bc_g = g_bc + ((size_t)b*LL + k*CL)*DS;

    #define P1_PRE(T, bf)                                                      \
    {                                                                          \
        _Pragma("unroll")                                                      \
        for (int i = 0; i < 2; i++) {                                          \
            int e = tid + 128*i;                                               \
            int jj = e >> 3, c = e & 7;                                        \
            cpa8(du_sm + (unsigned)((((bf)*TSTEP + jj)*8 + c)*8),              \
                 du_g + (size_t)((T)*TSTEP + jj)*DI + c);                      \
        }                                                                      \
        _Pragma("unroll")                                                      \
        for (int i = 0; i < 2; i++) {                                          \
            int e = tid + 128*i;                                               \
            int jj = e >> 3, q = e & 7;                                        \
            cpa16(bc_sm + (unsigned)((((bf)*TSTEP + jj)*DS + q*2)*8),          \
                  bc_g + (size_t)((T)*TSTEP + jj)*DS + q*2);                   \
        }                                                                      \
    }

    P1_PRE(0, 0); cp_commit();
    P1_PRE(1, 1); cp_commit();

    float h = 0.f, Ssum = 0.f;
    for (int T = 0; T < PTILES; T++) {
        if (T < PTILES-1) cp_wait1(); else cp_wait0();
        __syncthreads();
        if (T + 2 < PTILES) { P1_PRE(T+2, (T+2)%3); cp_commit(); }
        int bf = T % 3;
        #pragma unroll
        for (int jj = 0; jj < TSTEP; jj++) {
            float2 du = du2[bf][jj][ch];
            float2 bc = bc2[bf][jj][n];
            float dA = __expf(du.x * a_coef);
            h = fmaf(dA, h, du.x * du.y * bc.x);
            Ssum += du.x;
        }
    }
    #undef P1_PRE

    g_E[((size_t)(b*CH + k)*DI + d)*DS + n] = h;
    if (n == 0) g_Ssum[(size_t)(b*CH + k)*DI + d] = Ssum;
}

// =======================================================================
// scan pass 2: compose chunk carries
// =======================================================================
__global__ void __launch_bounds__(256) scan_p2_k(const float* __restrict__ A_logs)
{
    int t = blockIdx.x * 256 + threadIdx.x;
    int n  = t & 15;
    int dd = (t >> 4) % DI;
    int b  = t / (DI*DS);
    float a_coef = -__expf(A_logs[dd*DS + n]);
    float H = 0.f;
    for (int k = 0; k < CH; k++) {
        g_hin[((size_t)(b*CH + k)*DI + dd)*DS + n] = H;
        if (k < CH-1) {
            float S = g_Ssum[(size_t)(b*CH + k)*DI + dd];
            float E = g_E[((size_t)(b*CH + k)*DI + dd)*DS + n];
            H = fmaf(__expf(a_coef * S), H, E);
        }
    }
}

// =======================================================================
// scan pass 3: full scan within chunk, seeded, outputs y
// =======================================================================
__global__ void __launch_bounds__(128) scan_p3_k(const float* __restrict__ A_logs,
        const float* __restrict__ Ds, const int* __restrict__ scan_path)
{
    __shared__ __align__(16) float2 du2[2][TSTEP][8];
    __shared__ __align__(16) float2 bc2[2][TSTEP][DS];
    __shared__ float  ps[TSTEP*8*17];
    __shared__ float  s_D[8];

    int blk = blockIdx.x;
    int k  = blk % CH;
    int cb = blk / CH;
    int b  = cb / 48;
    int d0 = (cb % 48) * 8;
    int tid = threadIdx.x;
    int wid = tid >> 5, lane = tid & 31;
    int g = lane >> 4, n = lane & 15;
    int ch = wid*2 + g;
    int d = d0 + ch;

    float a_coef = -__expf(A_logs[d*DS + n]);
    if (tid < 8) s_D[tid] = Ds[d0 + tid];

    unsigned du_sm = (unsigned)__cvta_generic_to_shared(&du2[0][0][0]);
    unsigned bc_sm = (unsigned)__cvta_generic_to_shared(&bc2[0][0][0]);
    const float2* du_g = g_du + ((size_t)b*LL + k*CL)*DI + d0;
    const float2* bc_g = g_bc + ((size_t)b*LL + k*CL)*DS;

    {
        #pragma unroll
        for (int i = 0; i < 2; i++) {
            int e = tid + 128*i;
            int jj = e >> 3, c = e & 7;
            cpa8(du_sm + (unsigned)((jj*8 + c)*8), du_g + (size_t)jj*DI + c);
        }
        #pragma unroll
        for (int i = 0; i < 2; i++) {
            int e = tid + 128*i;
            int jj = e >> 3, q = e & 7;
            cpa16(bc_sm + (unsigned)((jj*DS + q*2)*8), bc_g + (size_t)jj*DS + q*2);
        }
        cp_commit();
    }

    float h = g_hin[((size_t)(b*CH + k)*DI + d)*DS + n];
    int buf = 0;
    for (int T = 0; T < PTILES; T++) {
        if (T + 1 < PTILES) {
            int o = (buf^1) * TSTEP;
            #pragma unroll
            for (int i = 0; i < 2; i++) {
                int e = tid + 128*i;
                int jj = e >> 3, c = e & 7;
                cpa8(du_sm + (unsigned)(((o+jj)*8 + c)*8),
                     du_g + (size_t)((T+1)*TSTEP + jj)*DI + c);
            }
            #pragma unroll
            for (int i = 0; i < 2; i++) {
                int e = tid + 128*i;
                int jj = e >> 3, q = e & 7;
                cpa16(bc_sm + (unsigned)(((o+jj)*DS + q*2)*8),
                      bc_g + (size_t)((T+1)*TSTEP + jj)*DS + q*2);
            }
            cp_commit();
            cp_wait1();
        } else {
            cp_wait0();
        }
        __syncthreads();

        #pragma unroll 8
        for (int jj = 0; jj < TSTEP; jj++) {
            float2 du = du2[buf][jj][ch];
            float2 bc = bc2[buf][jj][n];
            float dA = __expf(du.x * a_coef);
            h = fmaf(dA, h, du.x * du.y * bc.x);
            ps[(jj*8 + ch)*17 + n] = h * bc.y;
        }
        __syncthreads();

        #pragma unroll
        for (int i = 0; i < 2; i++) {
            int e = tid + 128*i;
            int jj = e >> 3, c = e & 7;
            const float* p = &ps[(jj*8 + c)*17];
            float sum = p[0];
            #pragma unroll
            for (int kk = 1; kk < DS; kk++) sum += p[kk];
            float uval = du2[buf][jj][c].y;
            int pos = __ldg(&scan_path[k*CL + T*TSTEP + jj]);
            g_y[((size_t)b*LL + pos)*DI + d0 + c] = fmaf(uval, s_D[c], sum);
        }
        buf ^= 1;
    }
}

// ---------------- launch ----------------
extern "C" void kernel_launch(void* const* d_in, const int* in_sizes, int n_in,
                              void* d_out, int out_size)
{
    const float* x          = (const float*)d_in[0];
    const float* cond       = (const float*)d_in[1];
    const float* W_in       = (const float*)d_in[2];
    const float* W_con      = (const float*)d_in[3];
    const float* conv_w     = (const float*)d_in[4];
    const float* conv_b     = (const float*)d_in[5];
    const float* con_conv_w = (const float*)d_in[6];
    const float* con_conv_b = (const float*)d_in[7];
    const float* x_proj_w   = (const float*)d_in[8];
    const float* dt_proj_w  = (const float*)d_in[9];
    const float* dt_proj_b  = (const float*)d_in[10];
    const float* A_logs     = (const float*)d_in[11];
    const float* Ds         = (const float*)d_in[12];
    const float* ln_w       = (const float*)d_in[13];
    const float* ln_b       = (const float*)d_in[14];
    const float* W_out      = (const float*)d_in[15];
    const int*   scan_path  = (const int*)d_in[16];
    const int*   rev_scan   = (const int*)d_in[17];
    float* out = (float*)d_out;

    gemm_in_k<<<dim3(3*DI/64, NROWS/128), 256>>>(x, cond, W_in, W_con);
    dwconv_k<<<BB*DI, 256>>>(conv_w, conv_b, con_conv_w, con_conv_b);
    proj1_k<<<NROWS/64, 256>>>(x_proj_w, rev_scan);
    proj2_k<<<512, 256>>>(dt_proj_w, dt_proj_b, rev_scan);
    scan_p1_k<<<96*(CH-1), 128>>>(A_logs);
    scan_p2_k<<<(BB*DI*DS)/256, 256>>>(A_logs);
    scan_p3_k<<<96*CH, 128>>>(A_logs, Ds, scan_path);
    ln_stats_k<<<NROWS/8, 256>>>();
    gemm_out_k<<<dim3(DM/64, NROWS/128), 256>>>(W_out, ln_w, ln_b, out);
}

// round 14
// speedup vs baseline: 1.4645x; 1.0784x over previous
#include <cuda_runtime.h>
#include <cuda_bf16.h>
#include <cstdint>

#define BB 2
#define DM 192
#define DI 384
#define DS 16
#define DR 12
#define HH 64
#define WW 64
#define LL 4096
#define NROWS (BB*LL)   // 8192

#define TSTEP 32
#define CH 32
#define CL (LL/CH)          // 128 steps per chunk
#define PTILES (CL/TSTEP)   // 4 tiles per chunk

// ---------------- scratch ----------------
__device__ float  g_xa_pre[BB*DI*LL];
__device__ float  g_c_pre [BB*DI*LL];
__device__ float  g_xa_conv[BB*DI*LL];
__device__ float  g_s     [BB*DI*LL];
__device__ float  g_z     [NROWS*DI];
__device__ float2 g_du    [BB*LL*DI];
__device__ float2 g_bc    [BB*LL*DS];
__device__ float  g_y     [NROWS*DI];
__device__ float2 g_stats [NROWS];
__device__ float  g_xd    [NROWS*48];
__device__ float  g_E     [BB*CH*DI*DS];
__device__ float  g_Ssum  [BB*CH*DI];
__device__ float  g_hin   [BB*CH*DI*DS];
// bf16 split operands for gemm_in
__device__ __nv_bfloat16 g_Ah[2*NROWS*DM];   // x rows [0,8192), cond rows [8192,16384)
__device__ __nv_bfloat16 g_Al[2*NROWS*DM];
__device__ __nv_bfloat16 g_Wh[(2*DI+DI)*DM]; // W_in 768 rows, W_con 384 rows
__device__ __nv_bfloat16 g_Wl[(2*DI+DI)*DM];

__device__ __forceinline__ float silu_f(float v){ return v / (1.f + __expf(-v)); }

__device__ __forceinline__ void cpa4(unsigned dst, const void* src){
    asm volatile("cp.async.ca.shared.global [%0], [%1], 4;\n" :: "r"(dst), "l"(src));
}
__device__ __forceinline__ void cpa8(unsigned dst, const void* src){
    asm volatile("cp.async.ca.shared.global [%0], [%1], 8;\n" :: "r"(dst), "l"(src));
}
__device__ __forceinline__ void cpa16(unsigned dst, const void* src){
    asm volatile("cp.async.ca.shared.global [%0], [%1], 16;\n" :: "r"(dst), "l"(src));
}
__device__ __forceinline__ void cp_commit(){ asm volatile("cp.async.commit_group;\n"); }
__device__ __forceinline__ void cp_wait1(){ asm volatile("cp.async.wait_group 1;\n"); }
__device__ __forceinline__ void cp_wait0(){ asm volatile("cp.async.wait_group 0;\n"); }

__device__ __forceinline__ void mma_bf16(float* c, const uint32_t* a, const uint32_t* b){
    asm volatile("mma.sync.aligned.m16n8k16.row.col.f32.bf16.bf16.f32 "
        "{%0,%1,%2,%3}, {%4,%5,%6,%7}, {%8,%9}, {%0,%1,%2,%3};"
        : "+f"(c[0]), "+f"(c[1]), "+f"(c[2]), "+f"(c[3])
        : "r"(a[0]), "r"(a[1]), "r"(a[2]), "r"(a[3]), "r"(b[0]), "r"(b[1]));
}

// =======================================================================
// cvt_k: fp32 -> bf16 hi/lo split for x, cond, W_in, W_con (float2 grain)
// =======================================================================
__global__ void __launch_bounds__(256) cvt_k(const float* __restrict__ x,
        const float* __restrict__ cond, const float* __restrict__ W_in,
        const float* __restrict__ W_con)
{
    int e = blockIdx.x * 256 + threadIdx.x;   // float2 index, 0..1683455
    const float* src;
    __nv_bfloat162 *dh, *dl;
    if (e < 786432) {
        src = x + 2*(size_t)e;
        dh = (__nv_bfloat162*)g_Ah + e; dl = (__nv_bfloat162*)g_Al + e;
    } else if (e < 1572864) {
        src = cond + 2*(size_t)(e - 786432);
        dh = (__nv_bfloat162*)g_Ah + e; dl = (__nv_bfloat162*)g_Al + e;
    } else {
        int q = e - 1572864;
        src = (q < 73728) ? (W_in + 2*(size_t)q) : (W_con + 2*(size_t)(q - 73728));
        dh = (__nv_bfloat162*)g_Wh + q; dl = (__nv_bfloat162*)g_Wl + q;
    }
    float2 v = *(const float2*)src;
    __nv_bfloat16 hx = __float2bfloat16_rn(v.x);
    __nv_bfloat16 hy = __float2bfloat16_rn(v.y);
    *dh = __nv_bfloat162(hx, hy);
    *dl = __nv_bfloat162(__float2bfloat16_rn(v.x - __bfloat162float(hx)),
                         __float2bfloat16_rn(v.y - __bfloat162float(hy)));
}

// =======================================================================
// gemm_in_mma: both input GEMMs via mma.sync bf16 split (3 mma/product).
// 128x64 tile, 8 warps (4m x 2n), warp tile 32x32, K chunk 16, cp.async x2.
// =======================================================================
#define GA_ROW 48                       // bytes per smem row (16 bf16 + pad)
#define G_AH 0
#define G_AL (128*GA_ROW)               // 6144
#define G_BH (2*128*GA_ROW)             // 12288
#define G_BL (G_BH + 64*GA_ROW)         // 15360
#define GBUF (G_BH + 2*64*GA_ROW)       // 18432
#define GSMEM (2*GBUF)                  // 36864

__global__ void __launch_bounds__(256) gemm_in_mma()
{
    __shared__ __align__(128) char smem[GSMEM];
    int tid = threadIdx.x, lane = tid & 31, wid = tid >> 5;
    int n0 = blockIdx.x * 64;
    int m0 = blockIdx.y * 128;
    bool is_c = (n0 >= 2*DI);
    int nb = is_c ? n0 - 2*DI : n0;
    int arow0 = (is_c ? NROWS : 0) + m0;
    int wrow0 = (is_c ? 2*DI : 0) + nb;

    unsigned sbase = (unsigned)__cvta_generic_to_shared(smem);
    int g = lane >> 2, tg = lane & 3;
    int mw = (wid >> 1) * 32;
    int nw = (wid & 1) * 32;

    float c[2][4][4];
    #pragma unroll
    for (int i = 0; i < 2; i++)
        #pragma unroll
        for (int j = 0; j < 4; j++)
            #pragma unroll
            for (int q = 0; q < 4; q++) c[i][j][q] = 0.f;

    #define GIN_STAGE(kc, bf)                                                  \
    {                                                                          \
        _Pragma("unroll")                                                      \
        for (int i = 0; i < 2; i++) {                                          \
            int e = tid + 256*i;            /* 0..511 */                       \
            int mat = e >> 8, rr = (e >> 1) & 127, sg = e & 1;                 \
            const __nv_bfloat16* src = (mat ? g_Al : g_Ah)                     \
                + (size_t)(arow0 + rr)*DM + (kc)*16 + sg*8;                    \
            cpa16(sbase + (unsigned)((bf)*GBUF + mat*6144 + rr*GA_ROW + sg*16),\
                  src);                                                        \
        }                                                                      \
        {                                                                      \
            int e = tid;                    /* 0..255 */                       \
            int mat = e >> 7, rr = (e >> 1) & 63, sg = e & 1;                  \
            const __nv_bfloat16* src = (mat ? g_Wl : g_Wh)                     \
                + (size_t)(wrow0 + rr)*DM + (kc)*16 + sg*8;                    \
            cpa16(sbase + (unsigned)((bf)*GBUF + G_BH + mat*3072 + rr*GA_ROW + sg*16), \
                  src);                                                        \
        }                                                                      \
    }

    GIN_STAGE(0, 0); cp_commit();

    const int NCH = DM/16;   // 12
    for (int kc = 0; kc < NCH; kc++) {
        __syncthreads();     // prior compute done before overwriting its buffer
        if (kc + 1 < NCH) { GIN_STAGE(kc+1, (kc+1)&1); cp_commit(); cp_wait1(); }
        else              { cp_wait0(); }
        __syncthreads();
        const char* base = smem + (kc&1)*GBUF;

        int ko = 4*tg;       // byte offset of k = 2*tg (bf16)
        uint32_t ah[2][4], al[2][4], bh[4][2], bl[4][2];
        #pragma unroll
        for (int mt = 0; mt < 2; mt++) {
            int r = mw + mt*16 + g;
            ah[mt][0] = *(const uint32_t*)(base + G_AH + r*GA_ROW + ko);
            ah[mt][1] = *(const uint32_t*)(base + G_AH + (r+8)*GA_ROW + ko);
            ah[mt][2] = *(const uint32_t*)(base + G_AH + r*GA_ROW + ko + 16);
            ah[mt][3] = *(const uint32_t*)(base + G_AH + (r+8)*GA_ROW + ko + 16);
            al[mt][0] = *(const uint32_t*)(base + G_AL + r*GA_ROW + ko);
            al[mt][1] = *(const uint32_t*)(base + G_AL + (r+8)*GA_ROW + ko);
            al[mt][2] = *(const uint32_t*)(base + G_AL + r*GA_ROW + ko + 16);
            al[mt][3] = *(const uint32_t*)(base + G_AL + (r+8)*GA_ROW + ko + 16);
        }
        #pragma unroll
        for (int nt = 0; nt < 4; nt++) {
            int r = nw + nt*8 + g;
            bh[nt][0] = *(const uint32_t*)(base + G_BH + r*GA_ROW + ko);
            bh[nt][1] = *(const uint32_t*)(base + G_BH + r*GA_ROW + ko + 16);
            bl[nt][0] = *(const uint32_t*)(base + G_BL + r*GA_ROW + ko);
            bl[nt][1] = *(const uint32_t*)(base + G_BL + r*GA_ROW + ko + 16);
        }
        #pragma unroll
        for (int mt = 0; mt < 2; mt++)
            #pragma unroll
            for (int nt = 0; nt < 4; nt++) {
                mma_bf16(c[mt][nt], ah[mt], bh[nt]);
                mma_bf16(c[mt][nt], ah[mt], bl[nt]);
                mma_bf16(c[mt][nt], al[mt], bh[nt]);
            }
    }
    #undef GIN_STAGE

    __syncthreads();
    float* Sf = (float*)smem;
    bool transp = is_c || (n0 < DI);

    #pragma unroll
    for (int mt = 0; mt < 2; mt++)
        #pragma unroll
        for (int nt = 0; nt < 4; nt++) {
            int m  = mw + mt*16 + g;
            int cc = nw + nt*8 + 2*tg;
            if (transp) {
                Sf[cc*132 + m]       = c[mt][nt][0];
                Sf[(cc+1)*132 + m]   = c[mt][nt][1];
                Sf[cc*132 + m+8]     = c[mt][nt][2];
                Sf[(cc+1)*132 + m+8] = c[mt][nt][3];
            } else {
                Sf[m*66 + cc]        = silu_f(c[mt][nt][0]);
                Sf[m*66 + cc+1]      = silu_f(c[mt][nt][1]);
                Sf[(m+8)*66 + cc]    = silu_f(c[mt][nt][2]);
                Sf[(m+8)*66 + cc+1]  = silu_f(c[mt][nt][3]);
            }
        }
    __syncthreads();

    if (transp) {
        int b = m0 >> 12, l0 = m0 & 4095;
        float* dst = is_c ? g_c_pre : g_xa_pre;
        for (int e = tid; e < 64*128; e += 256) {
            int row = e >> 7, cc = e & 127;
            dst[((size_t)(b*DI + nb + row))*LL + l0 + cc] = Sf[row*132 + cc];
        }
    } else {
        int zoff = n0 - DI;
        for (int e = tid; e < 128*32; e += 256) {
            int row = e >> 5, q = e & 31;
            float2 vv = *(const float2*)&Sf[row*66 + q*2];
            *(float2*)&g_z[(size_t)(m0 + row)*DI + zoff + q*2] = vv;
        }
    }
}

#define AS_STRIDE 132
#define BS_STRIDE 68

// =======================================================================
// gemm_out: out = LN(y)*z @ W_out^T, LN applied on the fly, scalar FFMA.
// =======================================================================
__global__ void __launch_bounds__(256) gemm_out_k(const float* __restrict__ Bw,
        const float* __restrict__ ln_w, const float* __restrict__ ln_b,
        float* __restrict__ out)
{
    __shared__ __align__(16) float As[2][16*AS_STRIDE];
    __shared__ __align__(16) float Bs[2][16*BS_STRIDE];

    const int K = DI, N = DM;
    int tid = threadIdx.x;
    int tx = tid & 15, ty = tid >> 4;
    int n0 = blockIdx.x * 64;
    int m0 = blockIdx.y * 128;

    int am  = tid >> 1;
    int akq = (tid & 1) * 8;
    int bn  = tid >> 2;
    int bkq = (tid & 3) * 4;
    const float* yP = g_y + (size_t)(m0 + am) * K + akq;
    const float* zP = g_z + (size_t)(m0 + am) * K + akq;
    const float* bP = Bw  + (size_t)(n0 + bn) * K + bkq;
    float2 st = g_stats[m0 + am];

    float acc[8][4];
    #pragma unroll
    for (int i = 0; i < 8; i++)
        #pragma unroll
        for (int j = 0; j < 4; j++) acc[i][j] = 0.f;

    #define LOADA(c, r0, r1)                                                   \
    {                                                                          \
        int k = (c)*16;                                                        \
        float4 y0 = *(const float4*)(yP + k);                                  \
        float4 y1 = *(const float4*)(yP + k + 4);                              \
        float4 z0 = *(const float4*)(zP + k);                                  \
        float4 z1 = *(const float4*)(zP + k + 4);                              \
        float4 w0 = *(const float4*)(ln_w + k + akq);                          \
        float4 w1 = *(const float4*)(ln_w + k + akq + 4);                      \
        float4 lb0 = *(const float4*)(ln_b + k + akq);                         \
        float4 lb1 = *(const float4*)(ln_b + k + akq + 4);                     \
        r0.x = ((y0.x-st.x)*st.y*w0.x + lb0.x)*z0.x;                           \
        r0.y = ((y0.y-st.x)*st.y*w0.y + lb0.y)*z0.y;                           \
        r0.z = ((y0.z-st.x)*st.y*w0.z + lb0.z)*z0.z;                           \
        r0.w = ((y0.w-st.x)*st.y*w0.w + lb0.w)*z0.w;                           \
        r1.x = ((y1.x-st.x)*st.y*w1.x + lb1.x)*z1.x;                           \
        r1.y = ((y1.y-st.x)*st.y*w1.y + lb1.y)*z1.y;                           \
        r1.z = ((y1.z-st.x)*st.y*w1.z + lb1.z)*z1.z;                           \
        r1.w = ((y1.w-st.x)*st.y*w1.w + lb1.w)*z1.w;                           \
    }

    {
        float4 a0, a1;
        LOADA(0, a0, a1);
        float4 b0 = *(const float4*)(bP);
        As[0][(akq+0)*AS_STRIDE+am]=a0.x; As[0][(akq+1)*AS_STRIDE+am]=a0.y;
        As[0][(akq+2)*AS_STRIDE+am]=a0.z; As[0][(akq+3)*AS_STRIDE+am]=a0.w;
        As[0][(akq+4)*AS_STRIDE+am]=a1.x; As[0][(akq+5)*AS_STRIDE+am]=a1.y;
        As[0][(akq+6)*AS_STRIDE+am]=a1.z; As[0][(akq+7)*AS_STRIDE+am]=a1.w;
        Bs[0][(bkq+0)*BS_STRIDE+bn]=b0.x; Bs[0][(bkq+1)*BS_STRIDE+bn]=b0.y;
        Bs[0][(bkq+2)*BS_STRIDE+bn]=b0.z; Bs[0][(bkq+3)*BS_STRIDE+bn]=b0.w;
    }

    int buf = 0;
    const int nch = K / 16;
    for (int c = 0; c < nch; c++) {
        float4 na0, na1, nb0;
        if (c + 1 < nch) {
            LOADA(c+1, na0, na1);
            nb0 = *(const float4*)(bP + (c+1)*16);
        }
        __syncthreads();
        const float* Asr = As[buf];
        const float* Bsr = Bs[buf];
        #pragma unroll
        for (int kk = 0; kk < 16; kk++) {
            float4 a0 = *(const float4*)&Asr[kk*AS_STRIDE + ty*8];
            float4 a1 = *(const float4*)&Asr[kk*AS_STRIDE + ty*8 + 4];
            float4 b0 = *(const float4*)&Bsr[kk*BS_STRIDE + tx*4];
            float ar[8] = {a0.x,a0.y,a0.z,a0.w,a1.x,a1.y,a1.z,a1.w};
            float br[4] = {b0.x,b0.y,b0.z,b0.w};
            #pragma unroll
            for (int i = 0; i < 8; i++)
                #pragma unroll
                for (int j = 0; j < 4; j++)
                    acc[i][j] = fmaf(ar[i], br[j], acc[i][j]);
        }
        if (c + 1 < nch) {
            float* Asw = As[buf^1]; float* Bsw = Bs[buf^1];
            Asw[(akq+0)*AS_STRIDE+am]=na0.x; Asw[(akq+1)*AS_STRIDE+am]=na0.y;
            Asw[(akq+2)*AS_STRIDE+am]=na0.z; Asw[(akq+3)*AS_STRIDE+am]=na0.w;
            Asw[(akq+4)*AS_STRIDE+am]=na1.x; Asw[(akq+5)*AS_STRIDE+am]=na1.y;
            Asw[(akq+6)*AS_STRIDE+am]=na1.z; Asw[(akq+7)*AS_STRIDE+am]=na1.w;
            Bsw[(bkq+0)*BS_STRIDE+bn]=nb0.x; Bsw[(bkq+1)*BS_STRIDE+bn]=nb0.y;
            Bsw[(bkq+2)*BS_STRIDE+bn]=nb0.z; Bsw[(bkq+3)*BS_STRIDE+bn]=nb0.w;
            buf ^= 1;
        }
    }
    #undef LOADA

    #pragma unroll
    for (int i = 0; i < 8; i++) {
        int m = m0 + ty*8 + i;
        #pragma unroll
        for (int j = 0; j < 4; j++) {
            int n = n0 + tx*4 + j;
            out[(size_t)m*N + n] = acc[i][j];
        }
    }
}

// =======================================================================
// per-row LN stats
// =======================================================================
__global__ void __launch_bounds__(256) ln_stats_k()
{
    int row = blockIdx.x * 8 + (threadIdx.x >> 5);
    int lane = threadIdx.x & 31;
    const float* yr = g_y + (size_t)row * DI;
    float s = 0.f, q = 0.f;
    #pragma unroll
    for (int i = 0; i < 12; i++) {
        float v = yr[lane + 32*i];
        s += v; q += v*v;
    }
    #pragma unroll
    for (int o = 16; o > 0; o >>= 1) {
        s += __shfl_xor_sync(0xFFFFFFFFu, s, o);
        q += __shfl_xor_sync(0xFFFFFFFFu, q, o);
    }
    if (lane == 0) {
        float mu = s * (1.f / DI);
        float var = q * (1.f / DI) - mu*mu;
        g_stats[row] = make_float2(mu, rsqrtf(var + 1e-5f));
    }
}

// =======================================================================
// depthwise conv 3x3 + bias + silu for BOTH tensors
// =======================================================================
__global__ void __launch_bounds__(256) dwconv_k(const float* __restrict__ conv_w,
        const float* __restrict__ conv_b, const float* __restrict__ con_w,
        const float* __restrict__ con_b)
{
    __shared__ __align__(16) float imx[LL];
    __shared__ __align__(16) float imc[LL];
    int bd = blockIdx.x;
    int d  = bd % DI;
    const float* inx = g_xa_pre + (size_t)bd * LL;
    const float* inc = g_c_pre  + (size_t)bd * LL;
    float* outx = g_xa_conv + (size_t)bd * LL;
    float* outs = g_s       + (size_t)bd * LL;
    const float* wxp = conv_w + d * 9;
    const float* wcp = con_w  + d * 9;
    float bx = conv_b[d], bc = con_b[d];

    #pragma unroll
    for (int i = 0; i < 4; i++) {
        *(float4*)&imx[(threadIdx.x + 256*i)*4] = *(const float4*)&inx[(threadIdx.x + 256*i)*4];
        *(float4*)&imc[(threadIdx.x + 256*i)*4] = *(const float4*)&inc[(threadIdx.x + 256*i)*4];
    }
    float wx[9], wc[9];
    #pragma unroll
    for (int i = 0; i < 9; i++) { wx[i] = wxp[i]; wc[i] = wcp[i]; }
    __syncthreads();

    #pragma unroll
    for (int i = 0; i < 16; i++) {
        int l = threadIdx.x + 256*i;
        int y = l >> 6, x = l & 63;
        bool yl = y > 0, yh = y < 63, xl = x > 0, xh = x < 63;
        float ax = bx, ac = bc;
        if (yl) {
            if (xl) { ax = fmaf(imx[l-65], wx[0], ax); ac = fmaf(imc[l-65], wc[0], ac); }
            ax = fmaf(imx[l-64], wx[1], ax); ac = fmaf(imc[l-64], wc[1], ac);
            if (xh) { ax = fmaf(imx[l-63], wx[2], ax); ac = fmaf(imc[l-63], wc[2], ac); }
        }
        if (xl) { ax = fmaf(imx[l-1], wx[3], ax); ac = fmaf(imc[l-1], wc[3], ac); }
        ax = fmaf(imx[l], wx[4], ax); ac = fmaf(imc[l], wc[4], ac);
        if (xh) { ax = fmaf(imx[l+1], wx[5], ax); ac = fmaf(imc[l+1], wc[5], ac); }
        if (yh) {
            if (xl) { ax = fmaf(imx[l+63], wx[6], ax); ac = fmaf(imc[l+63], wc[6], ac); }
            ax = fmaf(imx[l+64], wx[7], ax); ac = fmaf(imc[l+64], wc[7], ac);
            if (xh) { ax = fmaf(imx[l+65], wx[8], ax); ac = fmaf(imc[l+65], wc[8], ac); }
        }
        float sa = silu_f(ax);
        outx[l] = sa;
        outs[l] = sa + silu_f(ac);
    }
}

// =======================================================================
// proj1: 64 px/block, x_proj GEMM (3-stage cp.async), write xd + B/C.
// =======================================================================
__global__ void __launch_bounds__(256) proj1_k(const float* __restrict__ x_proj_w,
        const int* __restrict__ rev_scan)
{
    __shared__ float xd[64*49];
    __shared__ __align__(16) struct { float sS[3][16*68]; float sB[3][16*48]; } a;

    int tid = threadIdx.x;
    int b   = blockIdx.x >> 6;
    int l0  = (blockIdx.x & 63) * 64;

    for (int e = tid; e < 3*16*48; e += 256) (&a.sB[0][0])[e] = 0.f;

    unsigned sS_b = (unsigned)__cvta_generic_to_shared(&a.sS[0][0]);
    unsigned sB_b = (unsigned)__cvta_generic_to_shared(&a.sB[0][0]);

    #define S1_PREFETCH(kc, bf)                                                \
    {                                                                          \
        int k = tid >> 4, px4 = tid & 15;                                      \
        cpa16(sS_b + (unsigned)(((bf)*16*68 + k*68 + px4*4)*4),                \
              g_s + ((size_t)(b*DI + (kc)*16 + k))*LL + l0 + px4*4);           \
        _Pragma("unroll")                                                      \
        for (int i = 0; i < 3; i++) {                                          \
            int e = tid + 256*i;                                               \
            int cc = e >> 4, kk = e & 15;                                      \
            if (cc < DR + 2*DS)                                                \
                cpa4(sB_b + (unsigned)(((bf)*16*48 + kk*48 + cc)*4),           \
                     x_proj_w + (size_t)cc*DI + (kc)*16 + kk);                 \
        }                                                                      \
    }

    __syncthreads();

    S1_PREFETCH(0, 0); cp_commit();
    S1_PREFETCH(1, 1); cp_commit();

    int tm = tid & 15, tn = tid >> 4;
    float acc[4][3];
    #pragma unroll
    for (int i = 0; i < 4; i++)
        #pragma unroll
        for (int j = 0; j < 3; j++) acc[i][j] = 0.f;

    const int NC1 = DI/16;
    for (int kc = 0; kc < NC1; kc++) {
        if (kc < NC1-1) cp_wait1(); else cp_wait0();
        __syncthreads();
        if (kc + 2 < NC1) { S1_PREFETCH(kc+2, (kc+2)%3); cp_commit(); }
        const float* sS = a.sS[kc%3];
        const float* sB = a.sB[kc%3];
        #pragma unroll
        for (int k = 0; k < 16; k++) {
            float4 av = *(const float4*)&sS[k*68 + tm*4];
            float b0 = sB[k*48 + tn*3 + 0];
            float b1 = sB[k*48 + tn*3 + 1];
            float b2 = sB[k*48 + tn*3 + 2];
            float ar[4] = {av.x, av.y, av.z, av.w};
            #pragma unroll
            for (int i = 0; i < 4; i++) {
                acc[i][0] = fmaf(ar[i], b0, acc[i][0]);
                acc[i][1] = fmaf(ar[i], b1, acc[i][1]);
                acc[i][2] = fmaf(ar[i], b2, acc[i][2]);
            }
        }
    }
    #pragma unroll
    for (int i = 0; i < 4; i++)
        #pragma unroll
        for (int j = 0; j < 3; j++)
            xd[(tm*4+i)*49 + tn*3+j] = acc[i][j];
    __syncthreads();

    for (int e = tid; e < 64*48; e += 256) {
        int row = e / 48, cc = e % 48;
        g_xd[((size_t)(b*LL) + l0 + row)*48 + cc] = xd[row*49 + cc];
    }

    int w = tid >> 5, lane = tid & 31;
    #pragma unroll
    for (int p = 0; p < 4; p++) {
        int px = w*8 + p*2 + (lane >> 4);
        int n  = lane & 15;
        int j  = __ldg(&rev_scan[l0 + px]);
        g_bc[((size_t)b*LL + j)*DS + n] =
            make_float2(xd[px*49 + DR + n], xd[px*49 + DR + DS + n]);
    }
    #undef S1_PREFETCH
}

// =======================================================================
// proj2: dt_proj + softplus + (delta,u) scatter. 512 blocks.
// =======================================================================
__global__ void __launch_bounds__(256) proj2_k(const float* __restrict__ dt_proj_w,
        const float* __restrict__ dt_proj_b, const int* __restrict__ rev_scan)
{
    __shared__ float sxd[32*13];
    __shared__ __align__(16) float xaT[3][32*36];

    int blk = blockIdx.x;
    int dh = blk & 1;
    int lt = (blk >> 1) & 127;
    int b  = blk >> 8;
    int l0 = lt * 32;
    int d0h = dh * 192;
    int tid = threadIdx.x, w = tid >> 5, lane = tid & 31;

    unsigned xa_b = (unsigned)__cvta_generic_to_shared(&xaT[0][0]);

    #define P2_PRE(cc, bf)                                                     \
    {                                                                          \
        int dd = tid >> 3, px4 = tid & 7;                                      \
        cpa16(xa_b + (unsigned)(((bf)*32*36 + dd*36 + px4*4)*4),               \
              g_xa_conv + ((size_t)(b*DI + d0h + (cc)*32 + dd))*LL + l0 + px4*4); \
    }

    P2_PRE(0, 0); cp_commit();
    P2_PRE(1, 1); cp_commit();

    for (int e = tid; e < 32*12; e += 256) {
        int row = e / 12, r = e % 12;
        sxd[row*13 + r] = g_xd[((size_t)(b*LL) + l0 + row)*48 + r];
    }

    const int NC2 = 6;
    for (int c = 0; c < NC2; c++) {
        if (c < NC2-1) cp_wait1(); else cp_wait0();
        __syncthreads();
        if (c + 2 < NC2) { P2_PRE(c+2, (c+2)%3); cp_commit(); }
        int d = d0h + c*32 + lane;
        float wr[DR];
        #pragma unroll
        for (int r = 0; r < DR; r++) wr[r] = __ldg(&dt_proj_w[(size_t)d*DR + r]);
        float bias = __ldg(&dt_proj_b[d]);
        const float* xa = xaT[c%3];
        #pragma unroll
        for (int p = 0; p < 4; p++) {
            int px = w*4 + p;
            float aa = bias;
            #pragma unroll
            for (int r = 0; r < DR; r++) aa = fmaf(wr[r], sxd[px*13 + r], aa);
            float delta = (aa > 20.f) ? aa : log1pf(__expf(aa));
            float uval  = xa[lane*36 + px];
            int j = __ldg(&rev_scan[l0 + px]);
            g_du[((size_t)b*LL + j)*DI + d] = make_float2(delta, uval);
        }
    }
    #undef P2_PRE
}

// =======================================================================
// scan pass 1: per-chunk end-state from h=0.
// =======================================================================
__global__ void __launch_bounds__(128) scan_p1_k(const float* __restrict__ A_logs)
{
    __shared__ __align__(16) float2 du2[3][TSTEP][8];
    __shared__ __align__(16) float2 bc2[3][TSTEP][DS];

    int blk = blockIdx.x;
    int k  = blk % (CH-1);
    int cb = blk / (CH-1);
    int b  = cb / 48;
    int d0 = (cb % 48) * 8;
    int tid = threadIdx.x;
    int wid = tid >> 5, lane = tid & 31;
    int g = lane >> 4, n = lane & 15;
    int ch = wid*2 + g;
    int d = d0 + ch;

    float a_coef = -__expf(A_logs[d*DS + n]);

    unsigned du_sm = (unsigned)__cvta_generic_to_shared(&du2[0][0][0]);
    unsigned bc_sm = (unsigned)__cvta_generic_to_shared(&bc2[0][0][0]);
    const float2* du_g = g_du + ((size_t)b*LL + k*CL)*DI + d0;
    const float2* bc_g = g_bc + ((size_t)b*LL + k*CL)*DS;

    #define P1_PRE(T, bf)                                                      \
    {                                                                          \
        _Pragma("unroll")                                                      \
        for (int i = 0; i < 2; i++) {                                          \
            int e = tid + 128*i;                                               \
            int jj = e >> 3, c = e & 7;                                        \
            cpa8(du_sm + (unsigned)((((bf)*TSTEP + jj)*8 + c)*8),              \
                 du_g + (size_t)((T)*TSTEP + jj)*DI + c);                      \
        }                                                                      \
        _Pragma("unroll")                                                      \
        for (int i = 0; i < 2; i++) {                                          \
            int e = tid + 128*i;                                               \
            int jj = e >> 3, q = e & 7;                                        \
            cpa16(bc_sm + (unsigned)((((bf)*TSTEP + jj)*DS + q*2)*8),          \
                  bc_g + (size_t)((T)*TSTEP + jj)*DS + q*2);                   \
        }                                                                      \
    }

    P1_PRE(0, 0); cp_commit();
    P1_PRE(1, 1); cp_commit();

    float h = 0.f, Ssum = 0.f;
    for (int T = 0; T < PTILES; T++) {
        if (T < PTILES-1) cp_wait1(); else cp_wait0();
        __syncthreads();
        if (T + 2 < PTILES) { P1_PRE(T+2, (T+2)%3); cp_commit(); }
        int bf = T % 3;
        #pragma unroll
        for (int jj = 0; jj < TSTEP; jj++) {
            float2 du = du2[bf][jj][ch];
            float2 bc = bc2[bf][jj][n];
            float dA = __expf(du.x * a_coef);
            h = fmaf(dA, h, du.x * du.y * bc.x);
            Ssum += du.x;
        }
    }
    #undef P1_PRE

    g_E[((size_t)(b*CH + k)*DI + d)*DS + n] = h;
    if (n == 0) g_Ssum[(size_t)(b*CH + k)*DI + d] = Ssum;
}

// =======================================================================
// scan pass 2: compose chunk carries
// =======================================================================
__global__ void __launch_bounds__(256) scan_p2_k(const float* __restrict__ A_logs)
{
    int t = blockIdx.x * 256 + threadIdx.x;
    int n  = t & 15;
    int dd = (t >> 4) % DI;
    int b  = t / (DI*DS);
    float a_coef = -__expf(A_logs[dd*DS + n]);
    float H = 0.f;
    for (int k = 0; k < CH; k++) {
        g_hin[((size_t)(b*CH + k)*DI + dd)*DS + n] = H;
        if (k < CH-1) {
            float S = g_Ssum[(size_t)(b*CH + k)*DI + dd];
            float E = g_E[((size_t)(b*CH + k)*DI + dd)*DS + n];
            H = fmaf(__expf(a_coef * S), H, E);
        }
    }
}

// =======================================================================
// scan pass 3: full scan within chunk, seeded, outputs y
// =======================================================================
__global__ void __launch_bounds__(128) scan_p3_k(const float* __restrict__ A_logs,
        const float* __restrict__ Ds, const int* __restrict__ scan_path)
{
    __shared__ __align__(16) float2 du2[2][TSTEP][8];
    __shared__ __align__(16) float2 bc2[2][TSTEP][DS];
    __shared__ float  ps[TSTEP*8*17];
    __shared__ float  s_D[8];

    int blk = blockIdx.x;
    int k  = blk % CH;
    int cb = blk / CH;
    int b  = cb / 48;
    int d0 = (cb % 48) * 8;
    int tid = threadIdx.x;
    int wid = tid >> 5, lane = tid & 31;
    int g = lane >> 4, n = lane & 15;
    int ch = wid*2 + g;
    int d = d0 + ch;

    float a_coef = -__expf(A_logs[d*DS + n]);
    if (tid < 8) s_D[tid] = Ds[d0 + tid];

    unsigned du_sm = (unsigned)__cvta_generic_to_shared(&du2[0][0][0]);
    unsigned bc_sm = (unsigned)__cvta_generic_to_shared(&bc2[0][0][0]);
    const float2* du_g = g_du + ((size_t)b*LL + k*CL)*DI + d0;
    const float2* bc_g = g_bc + ((size_t)b*LL + k*CL)*DS;

    {
        #pragma unroll
        for (int i = 0; i < 2; i++) {
            int e = tid + 128*i;
            int jj = e >> 3, c = e & 7;
            cpa8(du_sm + (unsigned)((jj*8 + c)*8), du_g + (size_t)jj*DI + c);
        }
        #pragma unroll
        for (int i = 0; i < 2; i++) {
            int e = tid + 128*i;
            int jj = e >> 3, q = e & 7;
            cpa16(bc_sm + (unsigned)((jj*DS + q*2)*8), bc_g + (size_t)jj*DS + q*2);
        }
        cp_commit();
    }

    float h = g_hin[((size_t)(b*CH + k)*DI + d)*DS + n];
    int buf = 0;
    for (int T = 0; T < PTILES; T++) {
        if (T + 1 < PTILES) {
            int o = (buf^1) * TSTEP;
            #pragma unroll
            for (int i = 0; i < 2; i++) {
                int e = tid + 128*i;
                int jj = e >> 3, c = e & 7;
                cpa8(du_sm + (unsigned)(((o+jj)*8 + c)*8),
                     du_g + (size_t)((T+1)*TSTEP + jj)*DI + c);
            }
            #pragma unroll
            for (int i = 0; i < 2; i++) {
                int e = tid + 128*i;
                int jj = e >> 3, q = e & 7;
                cpa16(bc_sm + (unsigned)(((o+jj)*DS + q*2)*8),
                      bc_g + (size_t)((T+1)*TSTEP + jj)*DS + q*2);
            }
            cp_commit();
            cp_wait1();
        } else {
            cp_wait0();
        }
        __syncthreads();

        #pragma unroll 8
        for (int jj = 0; jj < TSTEP; jj++) {
            float2 du = du2[buf][jj][ch];
            float2 bc = bc2[buf][jj][n];
            float dA = __expf(du.x * a_coef);
            h = fmaf(dA, h, du.x * du.y * bc.x);
            ps[(jj*8 + ch)*17 + n] = h * bc.y;
        }
        __syncthreads();

        #pragma unroll
        for (int i = 0; i < 2; i++) {
            int e = tid + 128*i;
            int jj = e >> 3, c = e & 7;
            const float* p = &ps[(jj*8 + c)*17];
            float sum = p[0];
            #pragma unroll
            for (int kk = 1; kk < DS; kk++) sum += p[kk];
            float uval = du2[buf][jj][c].y;
            int pos = __ldg(&scan_path[k*CL + T*TSTEP + jj]);
            g_y[((size_t)b*LL + pos)*DI + d0 + c] = fmaf(uval, s_D[c], sum);
        }
        buf ^= 1;
    }
}

// ---------------- launch ----------------
extern "C" void kernel_launch(void* const* d_in, const int* in_sizes, int n_in,
                              void* d_out, int out_size)
{
    const float* x          = (const float*)d_in[0];
    const float* cond       = (const float*)d_in[1];
    const float* W_in       = (const float*)d_in[2];
    const float* W_con      = (const float*)d_in[3];
    const float* conv_w     = (const float*)d_in[4];
    const float* conv_b     = (const float*)d_in[5];
    const float* con_conv_w = (const float*)d_in[6];
    const float* con_conv_b = (const float*)d_in[7];
    const float* x_proj_w   = (const float*)d_in[8];
    const float* dt_proj_w  = (const float*)d_in[9];
    const float* dt_proj_b  = (const float*)d_in[10];
    const float* A_logs     = (const float*)d_in[11];
    const float* Ds         = (const float*)d_in[12];
    const float* ln_w       = (const float*)d_in[13];
    const float* ln_b       = (const float*)d_in[14];
    const float* W_out      = (const float*)d_in[15];
    const int*   scan_path  = (const int*)d_in[16];
    const int*   rev_scan   = (const int*)d_in[17];
    float* out = (float*)d_out;

    cvt_k<<<6576, 256>>>(x, cond, W_in, W_con);
    gemm_in_mma<<<dim3(3*DI/64, NROWS/128), 256>>>();
    dwconv_k<<<BB*DI, 256>>>(conv_w, conv_b, con_conv_w, con_conv_b);
    proj1_k<<<NROWS/64, 256>>>(x_proj_w, rev_scan);
    proj2_k<<<512, 256>>>(dt_proj_w, dt_proj_b, rev_scan);
    scan_p1_k<<<96*(CH-1), 128>>>(A_logs);
    scan_p2_k<<<(BB*DI*DS)/256, 256>>>(A_logs);
    scan_p3_k<<<96*CH, 128>>>(A_logs, Ds, scan_path);
    ln_stats_k<<<NROWS/8, 256>>>();
    gemm_out_k<<<dim3(DM/64, NROWS/128), 256>>>(W_out, ln_w, ln_b, out);
}

// round 17
// speedup vs baseline: 1.5859x; 1.0829x over previous
#include <cuda_runtime.h>
#include <cuda_bf16.h>
#include <cstdint>

#define BB 2
#define DM 192
#define DI 384
#define DS 16
#define DR 12
#define HH 64
#define WW 64
#define LL 4096
#define NROWS (BB*LL)   // 8192

#define TSTEP 32
#define CH 32
#define CL (LL/CH)          // 128 steps per chunk
#define PTILES (CL/TSTEP)   // 4 tiles per chunk

// ---------------- scratch ----------------
__device__ float  g_xa_pre[BB*DI*LL];
__device__ float  g_c_pre [BB*DI*LL];
__device__ float  g_xa_conv[BB*DI*LL];
__device__ float  g_s     [BB*DI*LL];
__device__ float  g_z     [NROWS*DI];
__device__ float2 g_du    [BB*LL*DI];
__device__ float2 g_bc    [BB*LL*DS];
__device__ float  g_y     [NROWS*DI];
__device__ float2 g_stats [NROWS];
__device__ float  g_xd    [NROWS*48];
__device__ float  g_E     [BB*CH*DI*DS];
__device__ float  g_Ssum  [BB*CH*DI];
__device__ float  g_hin   [BB*CH*DI*DS];
// bf16 split operands
__device__ __nv_bfloat16 g_Ah[2*NROWS*DM];
__device__ __nv_bfloat16 g_Al[2*NROWS*DM];
__device__ __nv_bfloat16 g_Wh[(2*DI+DI)*DM];
__device__ __nv_bfloat16 g_Wl[(2*DI+DI)*DM];
__device__ __nv_bfloat16 g_Fh[NROWS*DI];     // LN(y)*z split
__device__ __nv_bfloat16 g_Fl[NROWS*DI];
__device__ __nv_bfloat16 g_WOh[DM*DI];       // W_out split
__device__ __nv_bfloat16 g_WOl[DM*DI];

__device__ __forceinline__ float silu_f(float v){ return v / (1.f + __expf(-v)); }

__device__ __forceinline__ void cpa4(unsigned dst, const void* src){
    asm volatile("cp.async.ca.shared.global [%0], [%1], 4;\n" :: "r"(dst), "l"(src));
}
__device__ __forceinline__ void cpa8(unsigned dst, const void* src){
    asm volatile("cp.async.ca.shared.global [%0], [%1], 8;\n" :: "r"(dst), "l"(src));
}
__device__ __forceinline__ void cpa16(unsigned dst, const void* src){
    asm volatile("cp.async.ca.shared.global [%0], [%1], 16;\n" :: "r"(dst), "l"(src));
}
__device__ __forceinline__ void cp_commit(){ asm volatile("cp.async.commit_group;\n"); }
__device__ __forceinline__ void cp_wait1(){ asm volatile("cp.async.wait_group 1;\n"); }
__device__ __forceinline__ void cp_wait0(){ asm volatile("cp.async.wait_group 0;\n"); }

__device__ __forceinline__ void mma_bf16(float* c, const uint32_t* a, const uint32_t* b){
    asm volatile("mma.sync.aligned.m16n8k16.row.col.f32.bf16.bf16.f32 "
        "{%0,%1,%2,%3}, {%4,%5,%6,%7}, {%8,%9}, {%0,%1,%2,%3};"
        : "+f"(c[0]), "+f"(c[1]), "+f"(c[2]), "+f"(c[3])
        : "r"(a[0]), "r"(a[1]), "r"(a[2]), "r"(a[3]), "r"(b[0]), "r"(b[1]));
}

__device__ __forceinline__ void bf_split2(float a0, float a1,
        __nv_bfloat162& h, __nv_bfloat162& l){
    __nv_bfloat16 hx = __float2bfloat16_rn(a0);
    __nv_bfloat16 hy = __float2bfloat16_rn(a1);
    h = __nv_bfloat162(hx, hy);
    l = __nv_bfloat162(__float2bfloat16_rn(a0 - __bfloat162float(hx)),
                       __float2bfloat16_rn(a1 - __bfloat162float(hy)));
}

// =======================================================================
// cvt_k: fp32 -> bf16 hi/lo split for x, cond, W_in, W_con
// =======================================================================
__global__ void __launch_bounds__(256) cvt_k(const float* __restrict__ x,
        const float* __restrict__ cond, const float* __restrict__ W_in,
        const float* __restrict__ W_con)
{
    int e = blockIdx.x * 256 + threadIdx.x;
    const float* src;
    __nv_bfloat162 *dh, *dl;
    if (e < 786432) {
        src = x + 2*(size_t)e;
        dh = (__nv_bfloat162*)g_Ah + e; dl = (__nv_bfloat162*)g_Al + e;
    } else if (e < 1572864) {
        src = cond + 2*(size_t)(e - 786432);
        dh = (__nv_bfloat162*)g_Ah + e; dl = (__nv_bfloat162*)g_Al + e;
    } else {
        int q = e - 1572864;
        src = (q < 73728) ? (W_in + 2*(size_t)q) : (W_con + 2*(size_t)(q - 73728));
        dh = (__nv_bfloat162*)g_Wh + q; dl = (__nv_bfloat162*)g_Wl + q;
    }
    float2 v = *(const float2*)src;
    bf_split2(v.x, v.y, *dh, *dl);
}

// =======================================================================
// cvt2_k: LN(y)*z -> bf16 hi/lo, plus W_out split
// =======================================================================
__global__ void __launch_bounds__(256) cvt2_k(const float* __restrict__ ln_w,
        const float* __restrict__ ln_b, const float* __restrict__ W_out)
{
    int e = blockIdx.x * 256 + threadIdx.x;
    if (e < NROWS*DI/2) {
        int row = e / 192;
        int p   = e % 192;
        float2 yv = *(const float2*)&g_y[(size_t)row*DI + 2*p];
        float2 zv = *(const float2*)&g_z[(size_t)row*DI + 2*p];
        float2 wv = *(const float2*)&ln_w[2*p];
        float2 bv = *(const float2*)&ln_b[2*p];
        float2 st = g_stats[row];
        float a0 = ((yv.x - st.x)*st.y*wv.x + bv.x)*zv.x;
        float a1 = ((yv.y - st.x)*st.y*wv.y + bv.y)*zv.y;
        bf_split2(a0, a1, ((__nv_bfloat162*)g_Fh)[e], ((__nv_bfloat162*)g_Fl)[e]);
    } else {
        int q = e - NROWS*DI/2;
        if (q < DM*DI/2) {
            float2 v = *(const float2*)(W_out + 2*(size_t)q);
            bf_split2(v.x, v.y, ((__nv_bfloat162*)g_WOh)[q], ((__nv_bfloat162*)g_WOl)[q]);
        }
    }
}

// =======================================================================
// mma GEMM tile machinery (shared by gemm_in_mma / gemm_out_mma)
// =======================================================================
#define GA_ROW 48
#define G_AH 0
#define G_AL (128*GA_ROW)
#define G_BH (2*128*GA_ROW)
#define G_BL (G_BH + 64*GA_ROW)
#define GBUF (G_BH + 2*64*GA_ROW)
#define GSMEM (2*GBUF)

#define MMA_STAGE(Ah_, Al_, Wh_, Wl_, arow0_, wrow0_, Kdim, kc, bf)            \
{                                                                              \
    _Pragma("unroll")                                                          \
    for (int i = 0; i < 2; i++) {                                              \
        int e = tid + 256*i;                                                   \
        int mat = e >> 8, rr = (e >> 1) & 127, sg = e & 1;                     \
        const __nv_bfloat16* src = (mat ? Al_ : Ah_)                           \
            + (size_t)((arow0_) + rr)*(Kdim) + (kc)*16 + sg*8;                 \
        cpa16(sbase + (unsigned)((bf)*GBUF + mat*6144 + rr*GA_ROW + sg*16),    \
              src);                                                            \
    }                                                                          \
    {                                                                          \
        int e = tid;                                                           \
        int mat = e >> 7, rr = (e >> 1) & 63, sg = e & 1;                      \
        const __nv_bfloat16* src = (mat ? Wl_ : Wh_)                           \
            + (size_t)((wrow0_) + rr)*(Kdim) + (kc)*16 + sg*8;                 \
        cpa16(sbase + (unsigned)((bf)*GBUF + G_BH + mat*3072 + rr*GA_ROW + sg*16), \
              src);                                                            \
    }                                                                          \
}

#define MMA_MAIN(NCH)                                                          \
    for (int kc = 0; kc < (NCH); kc++) {                                       \
        __syncthreads();                                                       \
        if (kc + 1 < (NCH)) { MMA_STAGE_NEXT(kc+1, (kc+1)&1); cp_commit(); cp_wait1(); } \
        else                { cp_wait0(); }                                    \
        __syncthreads();                                                       \
        const char* base = smem + (kc&1)*GBUF;                                 \
        int ko = 4*tg;                                                         \
        uint32_t ah[2][4], al[2][4], bh[4][2], bl[4][2];                       \
        _Pragma("unroll")                                                      \
        for (int mt = 0; mt < 2; mt++) {                                       \
            int r = mw + mt*16 + g;                                            \
            ah[mt][0] = *(const uint32_t*)(base + G_AH + r*GA_ROW + ko);       \
            ah[mt][1] = *(const uint32_t*)(base + G_AH + (r+8)*GA_ROW + ko);   \
            ah[mt][2] = *(const uint32_t*)(base + G_AH + r*GA_ROW + ko + 16);  \
            ah[mt][3] = *(const uint32_t*)(base + G_AH + (r+8)*GA_ROW + ko + 16); \
            al[mt][0] = *(const uint32_t*)(base + G_AL + r*GA_ROW + ko);       \
            al[mt][1] = *(const uint32_t*)(base + G_AL + (r+8)*GA_ROW + ko);   \
            al[mt][2] = *(const uint32_t*)(base + G_AL + r*GA_ROW + ko + 16);  \
            al[mt][3] = *(const uint32_t*)(base + G_AL + (r+8)*GA_ROW + ko + 16); \
        }                                                                      \
        _Pragma("unroll")                                                      \
        for (int nt = 0; nt < 4; nt++) {                                       \
            int r = nw + nt*8 + g;                                             \
            bh[nt][0] = *(const uint32_t*)(base + G_BH + r*GA_ROW + ko);       \
            bh[nt][1] = *(const uint32_t*)(base + G_BH + r*GA_ROW + ko + 16);  \
            bl[nt][0] = *(const uint32_t*)(base + G_BL + r*GA_ROW + ko);       \
            bl[nt][1] = *(const uint32_t*)(base + G_BL + r*GA_ROW + ko + 16);  \
        }                                                                      \
        _Pragma("unroll")                                                      \
        for (int mt = 0; mt < 2; mt++)                                         \
            _Pragma("unroll")                                                  \
            for (int nt = 0; nt < 4; nt++) {                                   \
                mma_bf16(c[mt][nt], ah[mt], bh[nt]);                           \
                mma_bf16(c[mt][nt], ah[mt], bl[nt]);                           \
                mma_bf16(c[mt][nt], al[mt], bh[nt]);                           \
            }                                                                  \
    }

// =======================================================================
// gemm_in_mma: both input GEMMs via mma.sync bf16 split
// =======================================================================
__global__ void __launch_bounds__(256) gemm_in_mma()
{
    __shared__ __align__(128) char smem[GSMEM];
    int tid = threadIdx.x, lane = tid & 31, wid = tid >> 5;
    int n0 = blockIdx.x * 64;
    int m0 = blockIdx.y * 128;
    bool is_c = (n0 >= 2*DI);
    int nb = is_c ? n0 - 2*DI : n0;
    int arow0 = (is_c ? NROWS : 0) + m0;
    int wrow0 = (is_c ? 2*DI : 0) + nb;

    unsigned sbase = (unsigned)__cvta_generic_to_shared(smem);
    int g = lane >> 2, tg = lane & 3;
    int mw = (wid >> 1) * 32;
    int nw = (wid & 1) * 32;

    float c[2][4][4];
    #pragma unroll
    for (int i = 0; i < 2; i++)
        #pragma unroll
        for (int j = 0; j < 4; j++)
            #pragma unroll
            for (int q = 0; q < 4; q++) c[i][j][q] = 0.f;

    #define MMA_STAGE_NEXT(kc, bf) MMA_STAGE(g_Ah, g_Al, g_Wh, g_Wl, arow0, wrow0, DM, kc, bf)
    MMA_STAGE_NEXT(0, 0); cp_commit();
    MMA_MAIN(DM/16)
    #undef MMA_STAGE_NEXT

    __syncthreads();
    float* Sf = (float*)smem;
    bool transp = is_c || (n0 < DI);

    #pragma unroll
    for (int mt = 0; mt < 2; mt++)
        #pragma unroll
        for (int nt = 0; nt < 4; nt++) {
            int m  = mw + mt*16 + g;
            int cc = nw + nt*8 + 2*tg;
            if (transp) {
                Sf[cc*132 + m]       = c[mt][nt][0];
                Sf[(cc+1)*132 + m]   = c[mt][nt][1];
                Sf[cc*132 + m+8]     = c[mt][nt][2];
                Sf[(cc+1)*132 + m+8] = c[mt][nt][3];
            } else {
                Sf[m*66 + cc]        = silu_f(c[mt][nt][0]);
                Sf[m*66 + cc+1]      = silu_f(c[mt][nt][1]);
                Sf[(m+8)*66 + cc]    = silu_f(c[mt][nt][2]);
                Sf[(m+8)*66 + cc+1]  = silu_f(c[mt][nt][3]);
            }
        }
    __syncthreads();

    if (transp) {
        int b = m0 >> 12, l0 = m0 & 4095;
        float* dst = is_c ? g_c_pre : g_xa_pre;
        for (int e = tid; e < 64*128; e += 256) {
            int row = e >> 7, cc = e & 127;
            dst[((size_t)(b*DI + nb + row))*LL + l0 + cc] = Sf[row*132 + cc];
        }
    } else {
        int zoff = n0 - DI;
        for (int e = tid; e < 128*32; e += 256) {
            int row = e >> 5, q = e & 31;
            float2 vv = *(const float2*)&Sf[row*66 + q*2];
            *(float2*)&g_z[(size_t)(m0 + row)*DI + zoff + q*2] = vv;
        }
    }
}

// =======================================================================
// gemm_out_mma: out = LN(y)*z @ W_out^T via mma.sync bf16 split
// =======================================================================
__global__ void __launch_bounds__(256) gemm_out_mma(float* __restrict__ out)
{
    __shared__ __align__(128) char smem[GSMEM];
    int tid = threadIdx.x, lane = tid & 31, wid = tid >> 5;
    int n0 = blockIdx.x * 64;
    int m0 = blockIdx.y * 128;

    unsigned sbase = (unsigned)__cvta_generic_to_shared(smem);
    int g = lane >> 2, tg = lane & 3;
    int mw = (wid >> 1) * 32;
    int nw = (wid & 1) * 32;

    float c[2][4][4];
    #pragma unroll
    for (int i = 0; i < 2; i++)
        #pragma unroll
        for (int j = 0; j < 4; j++)
            #pragma unroll
            for (int q = 0; q < 4; q++) c[i][j][q] = 0.f;

    #define MMA_STAGE_NEXT(kc, bf) MMA_STAGE(g_Fh, g_Fl, g_WOh, g_WOl, m0, n0, DI, kc, bf)
    MMA_STAGE_NEXT(0, 0); cp_commit();
    MMA_MAIN(DI/16)
    #undef MMA_STAGE_NEXT

    #pragma unroll
    for (int mt = 0; mt < 2; mt++)
        #pragma unroll
        for (int nt = 0; nt < 4; nt++) {
            int m  = m0 + mw + mt*16 + g;
            int cc = n0 + nw + nt*8 + 2*tg;
            *(float2*)&out[(size_t)m*DM + cc]     = make_float2(c[mt][nt][0], c[mt][nt][1]);
            *(float2*)&out[(size_t)(m+8)*DM + cc] = make_float2(c[mt][nt][2], c[mt][nt][3]);
        }
}

// =======================================================================
// per-row LN stats
// =======================================================================
__global__ void __launch_bounds__(256) ln_stats_k()
{
    int row = blockIdx.x * 8 + (threadIdx.x >> 5);
    int lane = threadIdx.x & 31;
    const float* yr = g_y + (size_t)row * DI;
    float s = 0.f, q = 0.f;
    #pragma unroll
    for (int i = 0; i < 12; i++) {
        float v = yr[lane + 32*i];
        s += v; q += v*v;
    }
    #pragma unroll
    for (int o = 16; o > 0; o >>= 1) {
        s += __shfl_xor_sync(0xFFFFFFFFu, s, o);
        q += __shfl_xor_sync(0xFFFFFFFFu, q, o);
    }
    if (lane == 0) {
        float mu = s * (1.f / DI);
        float var = q * (1.f / DI) - mu*mu;
        g_stats[row] = make_float2(mu, rsqrtf(var + 1e-5f));
    }
}

// =======================================================================
// depthwise conv 3x3 + bias + silu for BOTH tensors
// =======================================================================
__global__ void __launch_bounds__(256) dwconv_k(const float* __restrict__ conv_w,
        const float* __restrict__ conv_b, const float* __restrict__ con_w,
        const float* __restrict__ con_b)
{
    __shared__ __align__(16) float imx[LL];
    __shared__ __align__(16) float imc[LL];
    int bd = blockIdx.x;
    int d  = bd % DI;
    const float* inx = g_xa_pre + (size_t)bd * LL;
    const float* inc = g_c_pre  + (size_t)bd * LL;
    float* outx = g_xa_conv + (size_t)bd * LL;
    float* outs = g_s       + (size_t)bd * LL;
    const float* wxp = conv_w + d * 9;
    const float* wcp = con_w  + d * 9;
    float bx = conv_b[d], bc = con_b[d];

    #pragma unroll
    for (int i = 0; i < 4; i++) {
        *(float4*)&imx[(threadIdx.x + 256*i)*4] = *(const float4*)&inx[(threadIdx.x + 256*i)*4];
        *(float4*)&imc[(threadIdx.x + 256*i)*4] = *(const float4*)&inc[(threadIdx.x + 256*i)*4];
    }
    float wx[9], wc[9];
    #pragma unroll
    for (int i = 0; i < 9; i++) { wx[i] = wxp[i]; wc[i] = wcp[i]; }
    __syncthreads();

    #pragma unroll
    for (int i = 0; i < 16; i++) {
        int l = threadIdx.x + 256*i;
        int y = l >> 6, x = l & 63;
        bool yl = y > 0, yh = y < 63, xl = x > 0, xh = x < 63;
        float ax = bx, ac = bc;
        if (yl) {
            if (xl) { ax = fmaf(imx[l-65], wx[0], ax); ac = fmaf(imc[l-65], wc[0], ac); }
            ax = fmaf(imx[l-64], wx[1], ax); ac = fmaf(imc[l-64], wc[1], ac);
            if (xh) { ax = fmaf(imx[l-63], wx[2], ax); ac = fmaf(imc[l-63], wc[2], ac); }
        }
        if (xl) { ax = fmaf(imx[l-1], wx[3], ax); ac = fmaf(imc[l-1], wc[3], ac); }
        ax = fmaf(imx[l], wx[4], ax); ac = fmaf(imc[l], wc[4], ac);
        if (xh) { ax = fmaf(imx[l+1], wx[5], ax); ac = fmaf(imc[l+1], wc[5], ac); }
        if (yh) {
            if (xl) { ax = fmaf(imx[l+63], wx[6], ax); ac = fmaf(imc[l+63], wc[6], ac); }
            ax = fmaf(imx[l+64], wx[7], ax); ac = fmaf(imc[l+64], wc[7], ac);
            if (xh) { ax = fmaf(imx[l+65], wx[8], ax); ac = fmaf(imc[l+65], wc[8], ac); }
        }
        float sa = silu_f(ax);
        outx[l] = sa;
        outs[l] = sa + silu_f(ac);
    }
}

// =======================================================================
// proj1: 64 px/block, x_proj GEMM (3-stage cp.async), write xd + B/C.
// =======================================================================
__global__ void __launch_bounds__(256) proj1_k(const float* __restrict__ x_proj_w,
        const int* __restrict__ rev_scan)
{
    __shared__ float xd[64*49];
    __shared__ __align__(16) struct { float sS[3][16*68]; float sB[3][16*48]; } a;

    int tid = threadIdx.x;
    int b   = blockIdx.x >> 6;
    int l0  = (blockIdx.x & 63) * 64;

    for (int e = tid; e < 3*16*48; e += 256) (&a.sB[0][0])[e] = 0.f;

    unsigned sS_b = (unsigned)__cvta_generic_to_shared(&a.sS[0][0]);
    unsigned sB_b = (unsigned)__cvta_generic_to_shared(&a.sB[0][0]);

    #define S1_PREFETCH(kc, bf)                                                \
    {                                                                          \
        int k = tid >> 4, px4 = tid & 15;                                      \
        cpa16(sS_b + (unsigned)(((bf)*16*68 + k*68 + px4*4)*4),                \
              g_s + ((size_t)(b*DI + (kc)*16 + k))*LL + l0 + px4*4);           \
        _Pragma("unroll")                                                      \
        for (int i = 0; i < 3; i++) {                                          \
            int e = tid + 256*i;                                               \
            int cc = e >> 4, kk = e & 15;                                      \
            if (cc < DR + 2*DS)                                                \
                cpa4(sB_b + (unsigned)(((bf)*16*48 + kk*48 + cc)*4),           \
                     x_proj_w + (size_t)cc*DI + (kc)*16 + kk);                 \
        }                                                                      \
    }

    __syncthreads();

    S1_PREFETCH(0, 0); cp_commit();
    S1_PREFETCH(1, 1); cp_commit();

    int tm = tid & 15, tn = tid >> 4;
    float acc[4][3];
    #pragma unroll
    for (int i = 0; i < 4; i++)
        #pragma unroll
        for (int j = 0; j < 3; j++) acc[i][j] = 0.f;

    const int NC1 = DI/16;
    for (int kc = 0; kc < NC1; kc++) {
        if (kc < NC1-1) cp_wait1(); else cp_wait0();
        __syncthreads();
        if (kc + 2 < NC1) { S1_PREFETCH(kc+2, (kc+2)%3); cp_commit(); }
        const float* sS = a.sS[kc%3];
        const float* sB = a.sB[kc%3];
        #pragma unroll
        for (int k = 0; k < 16; k++) {
            float4 av = *(const float4*)&sS[k*68 + tm*4];
            float b0 = sB[k*48 + tn*3 + 0];
            float b1 = sB[k*48 + tn*3 + 1];
            float b2 = sB[k*48 + tn*3 + 2];
            float ar[4] = {av.x, av.y, av.z, av.w};
            #pragma unroll
            for (int i = 0; i < 4; i++) {
                acc[i][0] = fmaf(ar[i], b0, acc[i][0]);
                acc[i][1] = fmaf(ar[i], b1, acc[i][1]);
                acc[i][2] = fmaf(ar[i], b2, acc[i][2]);
            }
        }
    }
    #pragma unroll
    for (int i = 0; i < 4; i++)
        #pragma unroll
        for (int j = 0; j < 3; j++)
            xd[(tm*4+i)*49 + tn*3+j] = acc[i][j];
    __syncthreads();

    for (int e = tid; e < 64*48; e += 256) {
        int row = e / 48, cc = e % 48;
        g_xd[((size_t)(b*LL) + l0 + row)*48 + cc] = xd[row*49 + cc];
    }

    int w = tid >> 5, lane = tid & 31;
    #pragma unroll
    for (int p = 0; p < 4; p++) {
        int px = w*8 + p*2 + (lane >> 4);
        int n  = lane & 15;
        int j  = __ldg(&rev_scan[l0 + px]);
        g_bc[((size_t)b*LL + j)*DS + n] =
            make_float2(xd[px*49 + DR + n], xd[px*49 + DR + DS + n]);
    }
    #undef S1_PREFETCH
}

// =======================================================================
// proj2: dt_proj + softplus + (delta,u) scatter. 512 blocks.
// =======================================================================
__global__ void __launch_bounds__(256) proj2_k(const float* __restrict__ dt_proj_w,
        const float* __restrict__ dt_proj_b, const int* __restrict__ rev_scan)
{
    __shared__ float sxd[32*13];
    __shared__ __align__(16) float xaT[3][32*36];

    int blk = blockIdx.x;
    int dh = blk & 1;
    int lt = (blk >> 1) & 127;
    int b  = blk >> 8;
    int l0 = lt * 32;
    int d0h = dh * 192;
    int tid = threadIdx.x, w = tid >> 5, lane = tid & 31;

    unsigned xa_b = (unsigned)__cvta_generic_to_shared(&xaT[0][0]);

    #define P2_PRE(cc, bf)                                                     \
    {                                                                          \
        int dd = tid >> 3, px4 = tid & 7;                                      \
        cpa16(xa_b + (unsigned)(((bf)*32*36 + dd*36 + px4*4)*4),               \
              g_xa_conv + ((size_t)(b*DI + d0h + (cc)*32 + dd))*LL + l0 + px4*4); \
    }

    P2_PRE(0, 0); cp_commit();
    P2_PRE(1, 1); cp_commit();

    for (int e = tid; e < 32*12; e += 256) {
        int row = e / 12, r = e % 12;
        sxd[row*13 + r] = g_xd[((size_t)(b*LL) + l0 + row)*48 + r];
    }

    const int NC2 = 6;
    for (int c = 0; c < NC2; c++) {
        if (c < NC2-1) cp_wait1(); else cp_wait0();
        __syncthreads();
        if (c + 2 < NC2) { P2_PRE(c+2, (c+2)%3); cp_commit(); }
        int d = d0h + c*32 + lane;
        float wr[DR];
        #pragma unroll
        for (int r = 0; r < DR; r++) wr[r] = __ldg(&dt_proj_w[(size_t)d*DR + r]);
        float bias = __ldg(&dt_proj_b[d]);
        const float* xa = xaT[c%3];
        #pragma unroll
        for (int p = 0; p < 4; p++) {
            int px = w*4 + p;
            float aa = bias;
            #pragma unroll
            for (int r = 0; r < DR; r++) aa = fmaf(wr[r], sxd[px*13 + r], aa);
            float delta = (aa > 20.f) ? aa : log1pf(__expf(aa));
            float uval  = xa[lane*36 + px];
            int j = __ldg(&rev_scan[l0 + px]);
            g_du[((size_t)b*LL + j)*DI + d] = make_float2(delta, uval);
        }
    }
    #undef P2_PRE
}

// =======================================================================
// scan pass 1: per-chunk end-state from h=0.
// =======================================================================
__global__ void __launch_bounds__(128) scan_p1_k(const float* __restrict__ A_logs)
{
    __shared__ __align__(16) float2 du2[3][TSTEP][8];
    __shared__ __align__(16) float2 bc2[3][TSTEP][DS];

    int blk = blockIdx.x;
    int k  = blk % (CH-1);
    int cb = blk / (CH-1);
    int b  = cb / 48;
    int d0 = (cb % 48) * 8;
    int tid = threadIdx.x;
    int wid = tid >> 5, lane = tid & 31;
    int g = lane >> 4, n = lane & 15;
    int ch = wid*2 + g;
    int d = d0 + ch;

    float a_coef = -__expf(A_logs[d*DS + n]);

    unsigned du_sm = (unsigned)__cvta_generic_to_shared(&du2[0][0][0]);
    unsigned bc_sm = (unsigned)__cvta_generic_to_shared(&bc2[0][0][0]);
    const float2* du_g = g_du + ((size_t)b*LL + k*CL)*DI + d0;
    const float2* bc_g = g_bc + ((size_t)b*LL + k*CL)*DS;

    #define P1_PRE(T, bf)                                                      \
    {                                                                          \
        _Pragma("unroll")                                                      \
        for (int i = 0; i < 2; i++) {                                          \
            int e = tid + 128*i;                                               \
            int jj = e >> 3, c = e & 7;                                        \
            cpa8(du_sm + (unsigned)((((bf)*TSTEP + jj)*8 + c)*8),              \
                 du_g + (size_t)((T)*TSTEP + jj)*DI + c);                      \
        }                                                                      \
        _Pragma("unroll")                                                      \
        for (int i = 0; i < 2; i++) {                                          \
            int e = tid + 128*i;                                               \
            int jj = e >> 3, q = e & 7;                                        \
            cpa16(bc_sm + (unsigned)((((bf)*TSTEP + jj)*DS + q*2)*8),          \
                  bc_g + (size_t)((T)*TSTEP + jj)*DS + q*2);                   \
        }                                                                      \
    }

    P1_PRE(0, 0); cp_commit();
    P1_PRE(1, 1); cp_commit();

    float h = 0.f, Ssum = 0.f;
    for (int T = 0; T < PTILES; T++) {
        if (T < PTILES-1) cp_wait1(); else cp_wait0();
        __syncthreads();
        if (T + 2 < PTILES) { P1_PRE(T+2, (T+2)%3); cp_commit(); }
        int bf = T % 3;
        #pragma unroll
        for (int jj = 0; jj < TSTEP; jj++) {
            float2 du = du2[bf][jj][ch];
            float2 bc = bc2[bf][jj][n];
            float dA = __expf(du.x * a_coef);
            h = fmaf(dA, h, du.x * du.y * bc.x);
            Ssum += du.x;
        }
    }
    #undef P1_PRE

    g_E[((size_t)(b*CH + k)*DI + d)*DS + n] = h;
    if (n == 0) g_Ssum[(size_t)(b*CH + k)*DI + d] = Ssum;
}

// =======================================================================
// scan pass 2: compose chunk carries
// =======================================================================
__global__ void __launch_bounds__(256) scan_p2_k(const float* __restrict__ A_logs)
{
    int t = blockIdx.x * 256 + threadIdx.x;
    int n  = t & 15;
    int dd = (t >> 4) % DI;
    int b  = t / (DI*DS);
    float a_coef = -__expf(A_logs[dd*DS + n]);
    float H = 0.f;
    for (int k = 0; k < CH; k++) {
        g_hin[((size_t)(b*CH + k)*DI + dd)*DS + n] = H;
        if (k < CH-1) {
            float S = g_Ssum[(size_t)(b*CH + k)*DI + dd];
            float E = g_E[((size_t)(b*CH + k)*DI + dd)*DS + n];
            H = fmaf(__expf(a_coef * S), H, E);
        }
    }
}

// =======================================================================
// scan pass 3: full scan within chunk, seeded, outputs y
// =======================================================================
__global__ void __launch_bounds__(128) scan_p3_k(const float* __restrict__ A_logs,
        const float* __restrict__ Ds, const int* __restrict__ scan_path)
{
    __shared__ __align__(16) float2 du2[2][TSTEP][8];
    __shared__ __align__(16) float2 bc2[2][TSTEP][DS];
    __shared__ float  ps[TSTEP*8*17];
    __shared__ float  s_D[8];

    int blk = blockIdx.x;
    int k  = blk % CH;
    int cb = blk / CH;
    int b  = cb / 48;
    int d0 = (cb % 48) * 8;
    int tid = threadIdx.x;
    int wid = tid >> 5, lane = tid & 31;
    int g = lane >> 4, n = lane & 15;
    int ch = wid*2 + g;
    int d = d0 + ch;

    float a_coef = -__expf(A_logs[d*DS + n]);
    if (tid < 8) s_D[tid] = Ds[d0 + tid];

    unsigned du_sm = (unsigned)__cvta_generic_to_shared(&du2[0][0][0]);
    unsigned bc_sm = (unsigned)__cvta_generic_to_shared(&bc2[0][0][0]);
    const float2* du_g = g_du + ((size_t)b*LL + k*CL)*DI + d0;
    const float2* bc_g = g_bc + ((size_t)b*LL + k*CL)*DS;

    {
        #pragma unroll
        for (int i = 0; i < 2; i++) {
            int e = tid + 128*i;
            int jj = e >> 3, c = e & 7;
            cpa8(du_sm + (unsigned)((jj*8 + c)*8), du_g + (size_t)jj*DI + c);
        }
        #pragma unroll
        for (int i = 0; i < 2; i++) {
            int e = tid + 128*i;
            int jj = e >> 3, q = e & 7;
            cpa16(bc_sm + (unsigned)((jj*DS + q*2)*8), bc_g + (size_t)jj*DS + q*2);
        }
        cp_commit();
    }

    float h = g_hin[((size_t)(b*CH + k)*DI + d)*DS + n];
    int buf = 0;
    for (int T = 0; T < PTILES; T++) {
        if (T + 1 < PTILES) {
            int o = (buf^1) * TSTEP;
            #pragma unroll
            for (int i = 0; i < 2; i++) {
                int e = tid + 128*i;
                int jj = e >> 3, c = e & 7;
                cpa8(du_sm + (unsigned)(((o+jj)*8 + c)*8),
                     du_g + (size_t)((T+1)*TSTEP + jj)*DI + c);
            }
            #pragma unroll
            for (int i = 0; i < 2; i++) {
                int e = tid + 128*i;
                int jj = e >> 3, q = e & 7;
                cpa16(bc_sm + (unsigned)(((o+jj)*DS + q*2)*8),
                      bc_g + (size_t)((T+1)*TSTEP + jj)*DS + q*2);
            }
            cp_commit();
            cp_wait1();
        } else {
            cp_wait0();
        }
        __syncthreads();

        #pragma unroll 8
        for (int jj = 0; jj < TSTEP; jj++) {
            float2 du = du2[buf][jj][ch];
            float2 bc = bc2[buf][jj][n];
            float dA = __expf(du.x * a_coef);
            h = fmaf(dA, h, du.x * du.y * bc.x);
            ps[(jj*8 + ch)*17 + n] = h * bc.y;
        }
        __syncthreads();

        #pragma unroll
        for (int i = 0; i < 2; i++) {
            int e = tid + 128*i;
            int jj = e >> 3, c = e & 7;
            const float* p = &ps[(jj*8 + c)*17];
            float sum = p[0];
            #pragma unroll
            for (int kk = 1; kk < DS; kk++) sum += p[kk];
            float uval = du2[buf][jj][c].y;
            int pos = __ldg(&scan_path[k*CL + T*TSTEP + jj]);
            g_y[((size_t)b*LL + pos)*DI + d0 + c] = fmaf(uval, s_D[c], sum);
        }
        buf ^= 1;
    }
}

// ---------------- launch ----------------
extern "C" void kernel_launch(void* const* d_in, const int* in_sizes, int n_in,
                              void* d_out, int out_size)
{
    const float* x          = (const float*)d_in[0];
    const float* cond       = (const float*)d_in[1];
    const float* W_in       = (const float*)d_in[2];
    const float* W_con      = (const float*)d_in[3];
    const float* conv_w     = (const float*)d_in[4];
    const float* conv_b     = (const float*)d_in[5];
    const float* con_conv_w = (const float*)d_in[6];
    const float* con_conv_b = (const float*)d_in[7];
    const float* x_proj_w   = (const float*)d_in[8];
    const float* dt_proj_w  = (const float*)d_in[9];
    const float* dt_proj_b  = (const float*)d_in[10];
    const float* A_logs     = (const float*)d_in[11];
    const float* Ds         = (const float*)d_in[12];
    const float* ln_w       = (const float*)d_in[13];
    const float* ln_b       = (const float*)d_in[14];
    const float* W_out      = (const float*)d_in[15];
    const int*   scan_path  = (const int*)d_in[16];
    const int*   rev_scan   = (const int*)d_in[17];
    float* out = (float*)d_out;

    cvt_k<<<6576, 256>>>(x, cond, W_in, W_con);
    gemm_in_mma<<<dim3(3*DI/64, NROWS/128), 256>>>();
    dwconv_k<<<BB*DI, 256>>>(conv_w, conv_b, con_conv_w, con_conv_b);
    proj1_k<<<NROWS/64, 256>>>(x_proj_w, rev_scan);
    proj2_k<<<512, 256>>>(dt_proj_w, dt_proj_b, rev_scan);
    scan_p1_k<<<96*(CH-1), 128>>>(A_logs);
    scan_p2_k<<<(BB*DI*DS)/256, 256>>>(A_logs);
    scan_p3_k<<<96*CH, 128>>>(A_logs, Ds, scan_path);
    ln_stats_k<<<NROWS/8, 256>>>();
    cvt2_k<<<6432, 256>>>(ln_w, ln_b, W_out);
    gemm_out_mma<<<dim3(DM/64, NROWS/128), 256>>>(out);
}